// round 3
// baseline (speedup 1.0000x reference)
#include <cuda_runtime.h>
#include <cstdint>

#define B_ 2
#define N_ 7
#define C_ 128
#define H_ 120
#define W_ 360
#define HW_ (H_*W_)
#define HID_ 128
#define NSIM_ 48
#define OCOFF_ 56
#define ICOFF_ 176

// ---------------- scratch (device globals; no runtime alloc) ----------------
__device__ float g_mean[B_*C_*HW_];          // for_offset
__device__ float g_lr  [B_*C_*HW_];          // group-normed (NCHW)
__device__ float g_lrt [(size_t)B_*HW_*C_];  // group-normed (NHWC)
__device__ float g_norm[B_*HW_];             // per-pixel L2 norm of lr
__device__ float g_sim [B_*NSIM_*HW_];       // 48 similarity maps (NCHW)
__device__ float g_feat[B_*HID_*HW_];        // relu(conv1)
__device__ float g_off [B_*OCOFF_*HW_];      // off0(32) | off1(16) | off2(8)
__device__ float2 g_stats[32];               // (mu, rsigma) per (b, group)

// ---------------- f32x2 helpers (Blackwell packed fp32) ----------------
__device__ __forceinline__ unsigned long long dup2(float v) {
    unsigned long long r;
    unsigned u = __float_as_uint(v);
    asm("mov.b64 %0, {%1, %1};" : "=l"(r) : "r"(u));
    return r;
}
__device__ __forceinline__ void fma2(unsigned long long& d, unsigned long long a, unsigned long long b) {
    asm("fma.rn.f32x2 %0, %1, %2, %0;" : "+l"(d) : "l"(a), "l"(b));
}
__device__ __forceinline__ float2 unpack2(unsigned long long v) {
    unsigned lo, hi;
    asm("mov.b64 {%0, %1}, %2;" : "=r"(lo), "=r"(hi) : "l"(v));
    return make_float2(__uint_as_float(lo), __uint_as_float(hi));
}

// ---------------- 1. mean over N ----------------
__global__ void mean_kernel(const float* __restrict__ x) {
    int i = blockIdx.x * 256 + threadIdx.x;
    if (i >= B_*C_*HW_) return;
    int b = i / (C_*HW_);
    int r = i - b*(C_*HW_);
    const float* p = x + (size_t)b*N_*C_*HW_ + r;
    float s = 0.f;
#pragma unroll
    for (int n = 0; n < N_; n++) s += p[(size_t)n*C_*HW_];
    g_mean[i] = s * (1.f/N_);
}

// ---------------- 2a. GroupNorm stats (16 groups of 8 ch) ----------------
__global__ void gn_stats_kernel() {
    __shared__ double sd[256], sd2[256];
    int bg = blockIdx.x;  // b*16+g ; plane offset = bg*8*HW
    const float* p = g_mean + (size_t)bg * (8*HW_);
    double s = 0.0, ss = 0.0;
    const int n4 = (8*HW_)/4;
    for (int i = threadIdx.x; i < n4; i += 256) {
        float4 v = *(const float4*)(p + (size_t)i*4);
        s  += (double)v.x + v.y + v.z + v.w;
        ss += (double)v.x*v.x + (double)v.y*v.y + (double)v.z*v.z + (double)v.w*v.w;
    }
    sd[threadIdx.x] = s; sd2[threadIdx.x] = ss;
    __syncthreads();
    for (int o = 128; o; o >>= 1) {
        if (threadIdx.x < o) { sd[threadIdx.x] += sd[threadIdx.x+o]; sd2[threadIdx.x] += sd2[threadIdx.x+o]; }
        __syncthreads();
    }
    if (threadIdx.x == 0) {
        double n = 8.0*HW_;
        double mu = sd[0]/n;
        double var = sd2[0]/n - mu*mu;
        g_stats[bg] = make_float2((float)mu, rsqrtf((float)var + 1e-5f));
    }
}

// ---------------- 2b. GroupNorm apply -> lr (NCHW) and lr_t (NHWC) ----------------
__global__ void gn_apply_kernel(const float* __restrict__ gamma, const float* __restrict__ beta) {
    int i = blockIdx.x * 256 + threadIdx.x;
    if (i >= B_*C_*HW_) return;
    int b = i / (C_*HW_);
    int c = (i / HW_) % C_;
    int pix = i % HW_;
    float2 st = g_stats[b*16 + (c >> 3)];
    float v = (g_mean[i] - st.x) * st.y * gamma[c] + beta[c];
    g_lr[i] = v;
    g_lrt[((size_t)(b*HW_ + pix))*C_ + c] = v;
}

// ---------------- 3a. per-pixel L2 norm (warp per pixel) ----------------
__global__ void norm_kernel() {
    int wid = (blockIdx.x*256 + threadIdx.x) >> 5;
    int lane = threadIdx.x & 31;
    if (wid >= B_*HW_) return;
    float4 v = *(const float4*)&g_lrt[(size_t)wid*C_ + lane*4];
    float s = v.x*v.x + v.y*v.y + v.z*v.z + v.w*v.w;
#pragma unroll
    for (int o = 16; o; o >>= 1) s += __shfl_xor_sync(0xffffffffu, s, o);
    if (lane == 0) g_norm[wid] = fmaxf(sqrtf(s), 1e-8f);
}

// ---------------- 3b. cosine similarity, 7x7 dilated-2, minus center ----------------
__global__ void sim_kernel() {
    int wid = (blockIdx.x*256 + threadIdx.x) >> 5;
    int lane = threadIdx.x & 31;
    if (wid >= B_*HW_) return;
    int b = wid / HW_;
    int pix = wid - b*HW_;
    int y = pix / W_, xx = pix - y*W_;
    float4 cv = *(const float4*)&g_lrt[(size_t)wid*C_ + lane*4];
    float inv_cn = 1.f / g_norm[wid];
    int s = 0;
#pragma unroll
    for (int i = 0; i < 7; i++) {
#pragma unroll
        for (int j = 0; j < 7; j++) {
            if (i == 3 && j == 3) continue;
            int ny = y + 2*i - 6, nx = xx + 2*j - 6;
            float sim = 0.f;
            if ((unsigned)ny < H_ && (unsigned)nx < W_) {
                int npid = b*HW_ + ny*W_ + nx;
                float4 nv = *(const float4*)&g_lrt[(size_t)npid*C_ + lane*4];
                float d = cv.x*nv.x + cv.y*nv.y + cv.z*nv.z + cv.w*nv.w;
#pragma unroll
                for (int o = 16; o; o >>= 1) d += __shfl_xor_sync(0xffffffffu, d, o);
                sim = d * inv_cn / g_norm[npid];
            }
            if (lane == 0) g_sim[((size_t)(b*NSIM_ + s)*H_ + y)*W_ + xx] = sim;
            s++;
        }
    }
}

// ---------------- 4. fused offset convs (oc padded to 64), f32x2 ----------------
__global__ void __launch_bounds__(128) offconv_kernel(
        const float* __restrict__ w0, const float* __restrict__ b0a,
        const float* __restrict__ w1, const float* __restrict__ b1a,
        const float* __restrict__ w2, const float* __restrict__ b2a) {
    __shared__ __align__(16) float s_w[9*64];
    __shared__ float s_in[6*26];
    const int tid = threadIdx.x;
    const int b = blockIdx.z;
    const int x0 = blockIdx.x * 24, y0 = blockIdx.y * 4;
    const int pxg = tid & 15, ocg = tid >> 4;        // 16 px-groups x 8 oc-groups
    const int px = (pxg & 3) * 6, py = pxg >> 2;
    const int oc0 = ocg * 8;
    unsigned long long acc[4][6];
#pragma unroll
    for (int p = 0; p < 4; p++)
#pragma unroll
        for (int j = 0; j < 6; j++) acc[p][j] = 0ull;

    for (int ic = 0; ic < ICOFF_; ic++) {
        __syncthreads();
        if (tid < 64) {
            const float* wp;
            if (tid < 32)      wp = w0 + ((size_t)tid*ICOFF_ + ic)*9;
            else if (tid < 48) wp = w1 + ((size_t)(tid-32)*ICOFF_ + ic)*9;
            else if (tid < 56) wp = w2 + ((size_t)(tid-48)*ICOFF_ + ic)*9;
            else               wp = nullptr;
#pragma unroll
            for (int t = 0; t < 9; t++) s_w[t*64 + tid] = wp ? wp[t] : 0.f;
        } else {
            for (int i = tid - 64; i < 156; i += 64) {
                int r = i / 26, cl = i - r*26;
                int gy = y0 + r - 1, gx = x0 + cl - 1;
                float v = 0.f;
                if ((unsigned)gy < H_ && (unsigned)gx < W_) {
                    if (ic < C_) v = g_lr[((size_t)(b*C_ + ic)*H_ + gy)*W_ + gx];
                    else         v = g_sim[((size_t)(b*NSIM_ + (ic - C_))*H_ + gy)*W_ + gx];
                }
                s_in[r*26 + cl] = v;
            }
        }
        __syncthreads();
#pragma unroll
        for (int ky = 0; ky < 3; ky++) {
            unsigned long long ind[8];
#pragma unroll
            for (int j = 0; j < 8; j++) ind[j] = dup2(s_in[(py+ky)*26 + px + j]);
#pragma unroll
            for (int kx = 0; kx < 3; kx++) {
                const int t = ky*3 + kx;
                unsigned long long wA = *(const unsigned long long*)&s_w[t*64 + oc0];
                unsigned long long wB = *(const unsigned long long*)&s_w[t*64 + oc0 + 2];
                unsigned long long wC = *(const unsigned long long*)&s_w[t*64 + oc0 + 4];
                unsigned long long wD = *(const unsigned long long*)&s_w[t*64 + oc0 + 6];
#pragma unroll
                for (int j = 0; j < 6; j++) {
                    fma2(acc[0][j], wA, ind[kx+j]);
                    fma2(acc[1][j], wB, ind[kx+j]);
                    fma2(acc[2][j], wC, ind[kx+j]);
                    fma2(acc[3][j], wD, ind[kx+j]);
                }
            }
        }
    }
    int oy = y0 + py;
#pragma unroll
    for (int p = 0; p < 4; p++) {
        int oc = oc0 + 2*p;
        if (oc >= OCOFF_) continue;
        float bb0 = (oc   < 32) ? b0a[oc]   : (oc   < 48 ? b1a[oc-32]   : b2a[oc-48]);
        float bb1 = (oc+1 < 32) ? b0a[oc+1] : (oc+1 < 48 ? b1a[oc-31] : b2a[oc-47]);
        float* o0 = g_off + ((size_t)(b*OCOFF_ + oc)*H_ + oy)*W_ + x0 + px;
        float* o1 = o0 + HW_;
#pragma unroll
        for (int j = 0; j < 6; j++) {
            float2 v = unpack2(acc[p][j]);
            o0[j] = v.x + bb0;
            o1[j] = v.y + bb1;
        }
    }
}

// ---------------- 5. big conv (898 ic -> 128 oc) + relu, f32x2 ----------------
__global__ void __launch_bounds__(256, 2) conv1_kernel(
        const float* __restrict__ x, const float* __restrict__ w, const float* __restrict__ bias) {
    __shared__ __align__(16) float s_w[9*128];
    __shared__ float s_in[6*26];
    const int tid = threadIdx.x;
    const int b = blockIdx.z;
    const int x0 = blockIdx.x * 24, y0 = blockIdx.y * 4;
    const int pxg = tid & 15, ocg = tid >> 4;        // 16 px-groups x 16 oc-groups
    const int px = (pxg & 3) * 6, py = pxg >> 2;
    const int oc0 = ocg * 8;
    unsigned long long acc[4][6];
#pragma unroll
    for (int p = 0; p < 4; p++)
#pragma unroll
        for (int j = 0; j < 6; j++) acc[p][j] = 0ull;

    for (int ic = 0; ic < 898; ic++) {
        __syncthreads();
        if (tid < 128) {
            const float* wp = w + ((size_t)tid*898 + ic)*9;   // 9 contiguous floats
#pragma unroll
            for (int t = 0; t < 9; t++) s_w[t*128 + tid] = wp[t];
        } else {
            for (int i = tid - 128; i < 156; i += 128) {
                int r = i / 26, cl = i - r*26;
                int gy = y0 + r - 1, gx = x0 + cl - 1;
                float v = 0.f;
                if ((unsigned)gy < H_ && (unsigned)gx < W_) {
                    if (ic < 896)       v = x[(((size_t)(b*N_ + (ic >> 7))*C_ + (ic & 127))*H_ + gy)*W_ + gx];
                    else if (ic == 896) v = gx*(2.f/(W_-1)) - 1.f;   // coord gx channel
                    else                v = gy*(2.f/(H_-1)) - 1.f;   // coord gy channel
                }
                s_in[r*26 + cl] = v;
            }
        }
        __syncthreads();
#pragma unroll
        for (int ky = 0; ky < 3; ky++) {
            unsigned long long ind[8];
#pragma unroll
            for (int j = 0; j < 8; j++) ind[j] = dup2(s_in[(py+ky)*26 + px + j]);
#pragma unroll
            for (int kx = 0; kx < 3; kx++) {
                const int t = ky*3 + kx;
                unsigned long long wA = *(const unsigned long long*)&s_w[t*128 + oc0];
                unsigned long long wB = *(const unsigned long long*)&s_w[t*128 + oc0 + 2];
                unsigned long long wC = *(const unsigned long long*)&s_w[t*128 + oc0 + 4];
                unsigned long long wD = *(const unsigned long long*)&s_w[t*128 + oc0 + 6];
#pragma unroll
                for (int j = 0; j < 6; j++) {
                    fma2(acc[0][j], wA, ind[kx+j]);
                    fma2(acc[1][j], wB, ind[kx+j]);
                    fma2(acc[2][j], wC, ind[kx+j]);
                    fma2(acc[3][j], wD, ind[kx+j]);
                }
            }
        }
    }
    int oy = y0 + py;
#pragma unroll
    for (int p = 0; p < 4; p++) {
        int oc = oc0 + 2*p;
        float bb0 = bias[oc], bb1 = bias[oc+1];
        float* o0 = g_feat + ((size_t)(b*HID_ + oc)*H_ + oy)*W_ + x0 + px;
        float* o1 = o0 + HW_;
#pragma unroll
        for (int j = 0; j < 6; j++) {
            float2 v = unpack2(acc[p][j]);
            o0[j] = fmaxf(v.x + bb0, 0.f);
            o1[j] = fmaxf(v.y + bb1, 0.f);
        }
    }
}

// ---------------- 6. fused triple deformable sampling + average ----------------
__device__ __forceinline__ float bilin(const float* __restrict__ f, float ix, float iy) {
    float fx = floorf(ix), fy = floorf(iy);
    float wx = ix - fx, wy = iy - fy;
    int xl = (int)fx, yl = (int)fy;
    int x0i = min(max(xl,     0), W_-1);
    int x1i = min(max(xl + 1, 0), W_-1);
    int y0i = min(max(yl,     0), H_-1);
    int y1i = min(max(yl + 1, 0), H_-1);
    float v00 = f[y0i*W_ + x0i], v01 = f[y0i*W_ + x1i];
    float v10 = f[y1i*W_ + x0i], v11 = f[y1i*W_ + x1i];
    return (v00*(1.f-wx) + v01*wx)*(1.f-wy) + (v10*(1.f-wx) + v11*wx)*wy;
}

__global__ void sample_kernel(float* __restrict__ out) {
    int i = blockIdx.x * 256 + threadIdx.x;
    if (i >= B_*C_*HW_) return;
    int xx = i % W_;
    int y  = (i / W_) % H_;
    int c  = (i / HW_) % C_;
    int b  = i / (C_*HW_);
    const float* offp = g_off + (size_t)b*OCOFF_*HW_ + y*W_ + xx;
    float ox0 = offp[(size_t)( 0 + (c>>3))*HW_], oy0 = offp[(size_t)(16 + (c>>3))*HW_];
    float ox1 = offp[(size_t)(32 + (c>>4))*HW_], oy1 = offp[(size_t)(40 + (c>>4))*HW_];
    float ox2 = offp[(size_t)(48 + (c>>5))*HW_], oy2 = offp[(size_t)(52 + (c>>5))*HW_];
    const float* f = g_feat + (size_t)(b*HID_ + c)*HW_;
    // grid math collapses exactly to ix = x + offx, iy = y + offy
    float s = bilin(f, xx + ox0, y + oy0)
            + bilin(f, xx + ox1, y + oy1)
            + bilin(f, xx + ox2, y + oy2);
    out[i] = s * (1.f/3.f);
}

// ---------------- launch ----------------
extern "C" void kernel_launch(void* const* d_in, const int* in_sizes, int n_in,
                              void* d_out, int out_size) {
    const float* x        = (const float*)d_in[0];
    const float* conv_w   = (const float*)d_in[1];
    const float* conv_b   = (const float*)d_in[2];
    const float* gn_gamma = (const float*)d_in[3];
    const float* gn_beta  = (const float*)d_in[4];
    const float* off_w    = (const float*)d_in[5];
    const float* off_b    = (const float*)d_in[6];
    const float* off1_w   = (const float*)d_in[7];
    const float* off1_b   = (const float*)d_in[8];
    const float* off2_w   = (const float*)d_in[9];
    const float* off2_b   = (const float*)d_in[10];
    float* out = (float*)d_out;

    const int total = B_*C_*HW_;
    mean_kernel<<<(total + 255)/256, 256>>>(x);
    gn_stats_kernel<<<32, 256>>>();
    gn_apply_kernel<<<(total + 255)/256, 256>>>(gn_gamma, gn_beta);
    norm_kernel<<<(B_*HW_ + 7)/8, 256>>>();
    sim_kernel<<<(B_*HW_ + 7)/8, 256>>>();
    offconv_kernel<<<dim3(15, 30, B_), 128>>>(off_w, off_b, off1_w, off1_b, off2_w, off2_b);
    conv1_kernel<<<dim3(15, 30, B_), 256>>>(x, conv_w, conv_b);
    sample_kernel<<<(total + 255)/256, 256>>>(out);
}

// round 7
// speedup vs baseline: 1.7070x; 1.7070x over previous
#include <cuda_runtime.h>
#include <cuda_bf16.h>
#include <cstdint>

#define B_ 2
#define N_ 7
#define C_ 128
#define H_ 120
#define W_ 360
#define HW_ (H_*W_)
#define HID_ 128
#define NSIM_ 48
#define OCOFF_ 56
#define ICOFF_ 176

// conv1 mma geometry
#define KP_ 960                    // padded K (898 -> 960, 15 chunks of 64)
#define KCH_ 15                    // 64-elem K chunks per tap
#define NITER_ (3*9*KCH_)          // 405 pipeline stages (3 passes x 9 taps x 15)
#define HP_ 122
#define WP_ 372
#define STG32_ 32768               // A(16KB)+B(16KB) per stage
#define SMEM_CONV_ (2*STG32_)

// ---------------- scratch (device globals; no runtime alloc) ----------------
__device__ float g_mean[B_*C_*HW_];
__device__ float g_lr  [B_*C_*HW_];
__device__ float g_lrt [(size_t)B_*HW_*C_];
__device__ float g_norm[B_*HW_];
__device__ float g_sim [B_*NSIM_*HW_];
__device__ float g_feat[B_*HID_*HW_];
__device__ float g_off [B_*OCOFF_*HW_];
__device__ float2 g_stats[32];
// padded NHWC bf16 input (hi/lo) and per-tap weights (hi/lo)
__device__ __align__(128) __nv_bfloat16 g_xt_hi[(size_t)B_*HP_*WP_*KP_];
__device__ __align__(128) __nv_bfloat16 g_xt_lo[(size_t)B_*HP_*WP_*KP_];
__device__ __align__(128) __nv_bfloat16 g_wt_hi[9*128*KP_];
__device__ __align__(128) __nv_bfloat16 g_wt_lo[9*128*KP_];

// ---------------- f32x2 helpers ----------------
__device__ __forceinline__ unsigned long long dup2(float v) {
    unsigned long long r;
    unsigned u = __float_as_uint(v);
    asm("mov.b64 %0, {%1, %1};" : "=l"(r) : "r"(u));
    return r;
}
__device__ __forceinline__ void fma2(unsigned long long& d, unsigned long long a, unsigned long long b) {
    asm("fma.rn.f32x2 %0, %1, %2, %0;" : "+l"(d) : "l"(a), "l"(b));
}
__device__ __forceinline__ float2 unpack2(unsigned long long v) {
    unsigned lo, hi;
    asm("mov.b64 {%0, %1}, %2;" : "=r"(lo), "=r"(hi) : "l"(v));
    return make_float2(__uint_as_float(lo), __uint_as_float(hi));
}

// ---------------- ptx helpers (cp.async / ldmatrix / mma.sync) ----------------
__device__ __forceinline__ uint32_t smem_u32(const void* p) {
    uint32_t a;
    asm("{ .reg .u64 t; cvta.to.shared.u64 t, %1; cvt.u32.u64 %0, t; }" : "=r"(a) : "l"(p));
    return a;
}
__device__ __forceinline__ void cp_async16(uint32_t dst, const void* src) {
    asm volatile("cp.async.cg.shared.global [%0], [%1], 16;" :: "r"(dst), "l"(src) : "memory");
}
__device__ __forceinline__ void cpa_commit() {
    asm volatile("cp.async.commit_group;" ::: "memory");
}
template<int N> __device__ __forceinline__ void cpa_wait() {
    asm volatile("cp.async.wait_group %0;" :: "n"(N) : "memory");
}
__device__ __forceinline__ void ldm_x4(uint32_t* r, uint32_t addr) {
    asm volatile("ldmatrix.sync.aligned.m8n8.x4.shared.b16 {%0,%1,%2,%3}, [%4];"
        : "=r"(r[0]), "=r"(r[1]), "=r"(r[2]), "=r"(r[3]) : "r"(addr));
}
__device__ __forceinline__ void mma_bf16(float* d, const uint32_t* a, uint32_t b0, uint32_t b1) {
    asm volatile("mma.sync.aligned.m16n8k16.row.col.f32.bf16.bf16.f32 "
        "{%0,%1,%2,%3}, {%4,%5,%6,%7}, {%8,%9}, {%0,%1,%2,%3};"
        : "+f"(d[0]), "+f"(d[1]), "+f"(d[2]), "+f"(d[3])
        : "r"(a[0]), "r"(a[1]), "r"(a[2]), "r"(a[3]), "r"(b0), "r"(b1));
}

// ---------------- 1. mean over N ----------------
__global__ void mean_kernel(const float* __restrict__ x) {
    int i = blockIdx.x * 256 + threadIdx.x;
    if (i >= B_*C_*HW_) return;
    int b = i / (C_*HW_);
    int r = i - b*(C_*HW_);
    const float* p = x + (size_t)b*N_*C_*HW_ + r;
    float s = 0.f;
#pragma unroll
    for (int n = 0; n < N_; n++) s += p[(size_t)n*C_*HW_];
    g_mean[i] = s * (1.f/N_);
}

// ---------------- 2a. GroupNorm stats ----------------
__global__ void gn_stats_kernel() {
    __shared__ double sd[256], sd2[256];
    int bg = blockIdx.x;
    const float* p = g_mean + (size_t)bg * (8*HW_);
    double s = 0.0, ss = 0.0;
    const int n4 = (8*HW_)/4;
    for (int i = threadIdx.x; i < n4; i += 256) {
        float4 v = *(const float4*)(p + (size_t)i*4);
        s  += (double)v.x + v.y + v.z + v.w;
        ss += (double)v.x*v.x + (double)v.y*v.y + (double)v.z*v.z + (double)v.w*v.w;
    }
    sd[threadIdx.x] = s; sd2[threadIdx.x] = ss;
    __syncthreads();
    for (int o = 128; o; o >>= 1) {
        if (threadIdx.x < o) { sd[threadIdx.x] += sd[threadIdx.x+o]; sd2[threadIdx.x] += sd2[threadIdx.x+o]; }
        __syncthreads();
    }
    if (threadIdx.x == 0) {
        double n = 8.0*HW_;
        double mu = sd[0]/n;
        double var = sd2[0]/n - mu*mu;
        g_stats[bg] = make_float2((float)mu, rsqrtf((float)var + 1e-5f));
    }
}

// ---------------- 2b. GroupNorm apply ----------------
__global__ void gn_apply_kernel(const float* __restrict__ gamma, const float* __restrict__ beta) {
    int i = blockIdx.x * 256 + threadIdx.x;
    if (i >= B_*C_*HW_) return;
    int b = i / (C_*HW_);
    int c = (i / HW_) % C_;
    int pix = i % HW_;
    float2 st = g_stats[b*16 + (c >> 3)];
    float v = (g_mean[i] - st.x) * st.y * gamma[c] + beta[c];
    g_lr[i] = v;
    g_lrt[((size_t)(b*HW_ + pix))*C_ + c] = v;
}

// ---------------- 3a. per-pixel L2 norm ----------------
__global__ void norm_kernel() {
    int wid = (blockIdx.x*256 + threadIdx.x) >> 5;
    int lane = threadIdx.x & 31;
    if (wid >= B_*HW_) return;
    float4 v = *(const float4*)&g_lrt[(size_t)wid*C_ + lane*4];
    float s = v.x*v.x + v.y*v.y + v.z*v.z + v.w*v.w;
#pragma unroll
    for (int o = 16; o; o >>= 1) s += __shfl_xor_sync(0xffffffffu, s, o);
    if (lane == 0) g_norm[wid] = fmaxf(sqrtf(s), 1e-8f);
}

// ---------------- 3b. cosine similarity ----------------
__global__ void sim_kernel() {
    int wid = (blockIdx.x*256 + threadIdx.x) >> 5;
    int lane = threadIdx.x & 31;
    if (wid >= B_*HW_) return;
    int b = wid / HW_;
    int pix = wid - b*HW_;
    int y = pix / W_, xx = pix - y*W_;
    float4 cv = *(const float4*)&g_lrt[(size_t)wid*C_ + lane*4];
    float inv_cn = 1.f / g_norm[wid];
    int s = 0;
#pragma unroll
    for (int i = 0; i < 7; i++) {
#pragma unroll
        for (int j = 0; j < 7; j++) {
            if (i == 3 && j == 3) continue;
            int ny = y + 2*i - 6, nx = xx + 2*j - 6;
            float sim = 0.f;
            if ((unsigned)ny < H_ && (unsigned)nx < W_) {
                int npid = b*HW_ + ny*W_ + nx;
                float4 nv = *(const float4*)&g_lrt[(size_t)npid*C_ + lane*4];
                float d = cv.x*nv.x + cv.y*nv.y + cv.z*nv.z + cv.w*nv.w;
#pragma unroll
                for (int o = 16; o; o >>= 1) d += __shfl_xor_sync(0xffffffffu, d, o);
                sim = d * inv_cn / g_norm[npid];
            }
            if (lane == 0) g_sim[((size_t)(b*NSIM_ + s)*H_ + y)*W_ + xx] = sim;
            s++;
        }
    }
}

// ---------------- 4. fused offset convs (oc padded to 64), f32x2 ----------------
__global__ void __launch_bounds__(128) offconv_kernel(
        const float* __restrict__ w0, const float* __restrict__ b0a,
        const float* __restrict__ w1, const float* __restrict__ b1a,
        const float* __restrict__ w2, const float* __restrict__ b2a) {
    __shared__ __align__(16) float s_w[9*64];
    __shared__ float s_in[6*26];
    const int tid = threadIdx.x;
    const int b = blockIdx.z;
    const int x0 = blockIdx.x * 24, y0 = blockIdx.y * 4;
    const int pxg = tid & 15, ocg = tid >> 4;
    const int px = (pxg & 3) * 6, py = pxg >> 2;
    const int oc0 = ocg * 8;
    unsigned long long acc[4][6];
#pragma unroll
    for (int p = 0; p < 4; p++)
#pragma unroll
        for (int j = 0; j < 6; j++) acc[p][j] = 0ull;

    for (int ic = 0; ic < ICOFF_; ic++) {
        __syncthreads();
        if (tid < 64) {
            const float* wp;
            if (tid < 32)      wp = w0 + ((size_t)tid*ICOFF_ + ic)*9;
            else if (tid < 48) wp = w1 + ((size_t)(tid-32)*ICOFF_ + ic)*9;
            else if (tid < 56) wp = w2 + ((size_t)(tid-48)*ICOFF_ + ic)*9;
            else               wp = nullptr;
#pragma unroll
            for (int t = 0; t < 9; t++) s_w[t*64 + tid] = wp ? wp[t] : 0.f;
        } else {
            for (int i = tid - 64; i < 156; i += 64) {
                int r = i / 26, cl = i - r*26;
                int gy = y0 + r - 1, gx = x0 + cl - 1;
                float v = 0.f;
                if ((unsigned)gy < H_ && (unsigned)gx < W_) {
                    if (ic < C_) v = g_lr[((size_t)(b*C_ + ic)*H_ + gy)*W_ + gx];
                    else         v = g_sim[((size_t)(b*NSIM_ + (ic - C_))*H_ + gy)*W_ + gx];
                }
                s_in[r*26 + cl] = v;
            }
        }
        __syncthreads();
#pragma unroll
        for (int ky = 0; ky < 3; ky++) {
            unsigned long long ind[8];
#pragma unroll
            for (int j = 0; j < 8; j++) ind[j] = dup2(s_in[(py+ky)*26 + px + j]);
#pragma unroll
            for (int kx = 0; kx < 3; kx++) {
                const int t = ky*3 + kx;
                unsigned long long wA = *(const unsigned long long*)&s_w[t*64 + oc0];
                unsigned long long wB = *(const unsigned long long*)&s_w[t*64 + oc0 + 2];
                unsigned long long wC = *(const unsigned long long*)&s_w[t*64 + oc0 + 4];
                unsigned long long wD = *(const unsigned long long*)&s_w[t*64 + oc0 + 6];
#pragma unroll
                for (int j = 0; j < 6; j++) {
                    fma2(acc[0][j], wA, ind[kx+j]);
                    fma2(acc[1][j], wB, ind[kx+j]);
                    fma2(acc[2][j], wC, ind[kx+j]);
                    fma2(acc[3][j], wD, ind[kx+j]);
                }
            }
        }
    }
    int oy = y0 + py;
#pragma unroll
    for (int p = 0; p < 4; p++) {
        int oc = oc0 + 2*p;
        if (oc >= OCOFF_) continue;
        float bb0 = (oc   < 32) ? b0a[oc]   : (oc   < 48 ? b1a[oc-32]   : b2a[oc-48]);
        float bb1 = (oc+1 < 32) ? b0a[oc+1] : (oc+1 < 48 ? b1a[oc-31] : b2a[oc-47]);
        float* o0 = g_off + ((size_t)(b*OCOFF_ + oc)*H_ + oy)*W_ + x0 + px;
        float* o1 = o0 + HW_;
#pragma unroll
        for (int j = 0; j < 6; j++) {
            float2 v = unpack2(acc[p][j]);
            o0[j] = v.x + bb0;
            o1[j] = v.y + bb1;
        }
    }
}

// ---------------- 5a. zero-fill padded input buffers ----------------
__global__ void zfill_kernel() {
    size_t n4 = ((size_t)B_*HP_*WP_*KP_*2) / 16;   // float4 count per buffer
    size_t i = (size_t)blockIdx.x * 256 + threadIdx.x;
    float4 z = make_float4(0.f, 0.f, 0.f, 0.f);
    if (i < n4)        ((float4*)g_xt_hi)[i] = z;
    else if (i < 2*n4) ((float4*)g_xt_lo)[i - n4] = z;
}

// ---------------- 5b. pack x (NCHW fp32 -> padded NHWC bf16 hi/lo) ----------------
__global__ void pack_x_kernel(const float* __restrict__ x) {
    __shared__ float t[32][33];
    int b  = blockIdx.z;
    int cg = blockIdx.y;           // 28 groups of 32 channels
    int pg = blockIdx.x;           // 1350 groups of 32 pixels
    int tx = threadIdx.x & 31, ty = threadIdx.x >> 5;   // 256 threads
    int pix0 = pg * 32;
    const float* src = x + ((size_t)b*896 + cg*32)*HW_ + pix0;
#pragma unroll
    for (int k = 0; k < 4; k++)
        t[ty + 8*k][tx] = src[(size_t)(ty + 8*k)*HW_ + tx];
    __syncthreads();
#pragma unroll
    for (int k = 0; k < 4; k++) {
        int p = pix0 + ty + 8*k;
        int yy = p / W_, xx = p - yy*W_;
        size_t ro = (((size_t)b*HP_ + yy + 1)*WP_ + (xx + 1))*KP_ + cg*32;
        float v = t[tx][ty + 8*k];
        __nv_bfloat16 h = __float2bfloat16(v);
        __nv_bfloat16 l = __float2bfloat16(v - __bfloat162float(h));
        g_xt_hi[ro + tx] = h;
        g_xt_lo[ro + tx] = l;
    }
}

// ---------------- 5c. coord channels (k=896 gx, k=897 gy) ----------------
__global__ void pack_coord_kernel() {
    int i = blockIdx.x * 256 + threadIdx.x;
    if (i >= B_*HW_) return;
    int b = i / HW_, p = i - b*HW_;
    int yy = p / W_, xx = p - yy*W_;
    size_t ro = (((size_t)b*HP_ + yy + 1)*WP_ + (xx + 1))*KP_;
    float gx = xx*(2.f/(W_-1)) - 1.f;
    float gy = yy*(2.f/(H_-1)) - 1.f;
    __nv_bfloat16 hx = __float2bfloat16(gx);
    __nv_bfloat16 hy = __float2bfloat16(gy);
    g_xt_hi[ro + 896] = hx;
    g_xt_lo[ro + 896] = __float2bfloat16(gx - __bfloat162float(hx));
    g_xt_hi[ro + 897] = hy;
    g_xt_lo[ro + 897] = __float2bfloat16(gy - __bfloat162float(hy));
}

// ---------------- 5d. pack weights (per tap, K-major, hi/lo) ----------------
__global__ void pack_w_kernel(const float* __restrict__ w) {
    int i = blockIdx.x * 256 + threadIdx.x;
    if (i >= 9*128*KP_) return;
    int tap = i / (128*KP_);
    int r = i - tap*(128*KP_);
    int oc = r / KP_, k = r - oc*KP_;
    float v = (k < 898) ? w[((size_t)oc*898 + k)*9 + tap] : 0.f;
    __nv_bfloat16 h = __float2bfloat16(v);
    g_wt_hi[i] = h;
    g_wt_lo[i] = __float2bfloat16(v - __bfloat162float(h));
}

// ---------------- 5e. conv1 via mma.sync bf16 (3-pass split implicit GEMM) ----------------
extern __shared__ char conv_smem[];

__global__ void __launch_bounds__(256, 2) conv1_mma_kernel(const float* __restrict__ bias) {
    const uint32_t sb = smem_u32(conv_smem);
    const int tid = threadIdx.x;
    const int b = blockIdx.z, y = blockIdx.y, x0 = blockIdx.x * 120;
    const int warp = tid >> 5, lane = tid & 31;
    const int m0 = (warp >> 1) * 32, n0 = (warp & 1) * 64;   // 4x2 warp grid

    float acc[2][8][4];
#pragma unroll
    for (int mt = 0; mt < 2; mt++)
#pragma unroll
        for (int nt = 0; nt < 8; nt++)
#pragma unroll
            for (int e = 0; e < 4; e++) acc[mt][nt][e] = 0.f;

    const int lrow = tid >> 1, cb = (tid & 1) * 4;   // 2 threads per 128B row, 4x16B each

    auto issue = [&](int j) {
        int pass = j / (9*KCH_);
        int rem  = j - pass*(9*KCH_);
        int tap  = rem / KCH_;
        int kc   = rem - tap*KCH_;
        const __nv_bfloat16* xa = (pass == 1) ? g_xt_lo : g_xt_hi;
        const __nv_bfloat16* wb = (pass == 2) ? g_wt_lo : g_wt_hi;
        int ky = tap / 3, kx = tap - ky*3;
        const char* Asrc = (const char*)(xa + (((size_t)b*HP_ + y + ky)*WP_ + (x0 + kx + lrow))*KP_ + kc*64);
        const char* Bsrc = (const char*)(wb + ((size_t)tap*128 + lrow)*KP_ + kc*64);
        uint32_t st = sb + (uint32_t)(j & 1) * STG32_;
        uint32_t Ad = st + (uint32_t)lrow*128;
        uint32_t Bd = Ad + 16384;
#pragma unroll
        for (int t = 0; t < 4; t++) {
            int c = cb + t;
            uint32_t o = (uint32_t)((c ^ (lrow & 7)) << 4);
            cp_async16(Ad + o, Asrc + c*16);
            cp_async16(Bd + o, Bsrc + c*16);
        }
    };

    issue(0); cpa_commit();

    const int g = lane >> 3, r = lane & 7;
    for (int i = 0; i < NITER_; i++) {
        if (i + 1 < NITER_) { issue(i + 1); cpa_commit(); cpa_wait<1>(); }
        else                { cpa_wait<0>(); }
        __syncthreads();

        uint32_t As = sb + (uint32_t)(i & 1) * STG32_;
        uint32_t Bs = As + 16384;
#pragma unroll
        for (int kt = 0; kt < 4; kt++) {
            const int c = kt*2 + (g >> 1);
            uint32_t a[2][4];
#pragma unroll
            for (int mt = 0; mt < 2; mt++) {
                int arow = m0 + mt*16 + ((g & 1) << 3) + r;
                ldm_x4(a[mt], As + (uint32_t)arow*128 + (uint32_t)((c ^ (arow & 7)) << 4));
            }
#pragma unroll
            for (int nt = 0; nt < 4; nt++) {
                uint32_t bq[4];
                int brow = n0 + nt*16 + ((g & 1) << 3) + r;
                ldm_x4(bq, Bs + (uint32_t)brow*128 + (uint32_t)((c ^ (brow & 7)) << 4));
#pragma unroll
                for (int mt = 0; mt < 2; mt++) {
                    mma_bf16(acc[mt][nt*2],     a[mt], bq[0], bq[2]);
                    mma_bf16(acc[mt][nt*2 + 1], a[mt], bq[1], bq[3]);
                }
            }
        }
        __syncthreads();
    }

    // epilogue: bias + relu -> NCHW g_feat.  d layout: d0/d1 at m=lane/4, d2/d3 at m+8;
    // n = (lane%4)*2 + {0,1}.
    const int qr = lane >> 2, qc = (lane & 3) * 2;
#pragma unroll
    for (int mt = 0; mt < 2; mt++) {
        int lm = m0 + mt*16 + qr;
#pragma unroll
        for (int nt = 0; nt < 8; nt++) {
            int oc = n0 + nt*8 + qc;
            float b0v = __ldg(bias + oc), b1v = __ldg(bias + oc + 1);
            float* p = g_feat + ((size_t)b*HID_ + oc)*HW_ + y*W_ + x0;
            if (lm < 120) {
                p[lm]       = fmaxf(acc[mt][nt][0] + b0v, 0.f);
                p[lm + HW_] = fmaxf(acc[mt][nt][1] + b1v, 0.f);
            }
            if (lm + 8 < 120) {
                p[lm + 8]       = fmaxf(acc[mt][nt][2] + b0v, 0.f);
                p[lm + 8 + HW_] = fmaxf(acc[mt][nt][3] + b1v, 0.f);
            }
        }
    }
}

// ---------------- 6. fused triple deformable sampling + average ----------------
__device__ __forceinline__ float bilin(const float* __restrict__ f, float ix, float iy) {
    float fx = floorf(ix), fy = floorf(iy);
    float wx = ix - fx, wy = iy - fy;
    int xl = (int)fx, yl = (int)fy;
    int x0i = min(max(xl,     0), W_-1);
    int x1i = min(max(xl + 1, 0), W_-1);
    int y0i = min(max(yl,     0), H_-1);
    int y1i = min(max(yl + 1, 0), H_-1);
    float v00 = f[y0i*W_ + x0i], v01 = f[y0i*W_ + x1i];
    float v10 = f[y1i*W_ + x0i], v11 = f[y1i*W_ + x1i];
    return (v00*(1.f-wx) + v01*wx)*(1.f-wy) + (v10*(1.f-wx) + v11*wx)*wy;
}

__global__ void sample_kernel(float* __restrict__ out) {
    int i = blockIdx.x * 256 + threadIdx.x;
    if (i >= B_*C_*HW_) return;
    int xx = i % W_;
    int y  = (i / W_) % H_;
    int c  = (i / HW_) % C_;
    int b  = i / (C_*HW_);
    const float* offp = g_off + (size_t)b*OCOFF_*HW_ + y*W_ + xx;
    float ox0 = offp[(size_t)( 0 + (c>>3))*HW_], oy0 = offp[(size_t)(16 + (c>>3))*HW_];
    float ox1 = offp[(size_t)(32 + (c>>4))*HW_], oy1 = offp[(size_t)(40 + (c>>4))*HW_];
    float ox2 = offp[(size_t)(48 + (c>>5))*HW_], oy2 = offp[(size_t)(52 + (c>>5))*HW_];
    const float* f = g_feat + (size_t)(b*HID_ + c)*HW_;
    float s = bilin(f, xx + ox0, y + oy0)
            + bilin(f, xx + ox1, y + oy1)
            + bilin(f, xx + ox2, y + oy2);
    out[i] = s * (1.f/3.f);
}

// ---------------- launch ----------------
extern "C" void kernel_launch(void* const* d_in, const int* in_sizes, int n_in,
                              void* d_out, int out_size) {
    const float* x        = (const float*)d_in[0];
    const float* conv_w   = (const float*)d_in[1];
    const float* conv_b   = (const float*)d_in[2];
    const float* gn_gamma = (const float*)d_in[3];
    const float* gn_beta  = (const float*)d_in[4];
    const float* off_w    = (const float*)d_in[5];
    const float* off_b    = (const float*)d_in[6];
    const float* off1_w   = (const float*)d_in[7];
    const float* off1_b   = (const float*)d_in[8];
    const float* off2_w   = (const float*)d_in[9];
    const float* off2_b   = (const float*)d_in[10];
    float* out = (float*)d_out;

    static bool attr_done = false;
    if (!attr_done) {
        cudaFuncSetAttribute(conv1_mma_kernel, cudaFuncAttributeMaxDynamicSharedMemorySize, SMEM_CONV_);
        attr_done = true;
    }

    const int total = B_*C_*HW_;

    // pack path for mma conv1
    {
        size_t n4 = ((size_t)B_*HP_*WP_*KP_*2) / 16;
        int zblocks = (int)((2*n4 + 255) / 256);
        zfill_kernel<<<zblocks, 256>>>();
        pack_x_kernel<<<dim3(HW_/32, 28, B_), 256>>>(x);
        pack_coord_kernel<<<(B_*HW_ + 255)/256, 256>>>();
        pack_w_kernel<<<(9*128*KP_ + 255)/256, 256>>>(conv_w);
    }

    mean_kernel<<<(total + 255)/256, 256>>>(x);
    gn_stats_kernel<<<32, 256>>>();
    gn_apply_kernel<<<(total + 255)/256, 256>>>(gn_gamma, gn_beta);
    norm_kernel<<<(B_*HW_ + 7)/8, 256>>>();
    sim_kernel<<<(B_*HW_ + 7)/8, 256>>>();
    offconv_kernel<<<dim3(15, 30, B_), 128>>>(off_w, off_b, off1_w, off1_b, off2_w, off2_b);
    conv1_mma_kernel<<<dim3(3, H_, B_), 256, SMEM_CONV_>>>(conv_b);
    sample_kernel<<<(total + 255)/256, 256>>>(out);
}

// round 8
// speedup vs baseline: 1.8728x; 1.0971x over previous
#include <cuda_runtime.h>
#include <cuda_bf16.h>
#include <cstdint>

#define B_ 2
#define N_ 7
#define C_ 128
#define H_ 120
#define W_ 360
#define HW_ (H_*W_)
#define HID_ 128
#define NSIM_ 48
#define OCOFF_ 56
#define ICOFF_ 176

// conv1 mma geometry
#define KP_ 960                    // padded K (898 -> 960, 15 chunks of 64)
#define HP_ 122
#define WP_ 372
#define ASZ_ 16640                 // A tile: 130 rows x 128B
#define BSZ_ 16384                 // B tile: 128 rows x 128B
#define NGRP_ 45                   // 15 kc x 3 ky
#define NSTG1_ 270                 // 45 groups x 6 B-stages
#define SMEM_CONV_ (3*ASZ_ + 3*BSZ_)   // Ahi0,Ahi1,Alo + B ring of 3 = 99072B

// ---------------- scratch (device globals; no runtime alloc) ----------------
__device__ float g_mean[B_*C_*HW_];
__device__ float g_lr  [B_*C_*HW_];
__device__ float g_lrt [(size_t)B_*HW_*C_];
__device__ float g_norm[B_*HW_];
__device__ float g_sim [B_*NSIM_*HW_];
__device__ float g_feat[B_*HID_*HW_];
__device__ float g_off [B_*OCOFF_*HW_];
__device__ float2 g_stats[32];
// padded NHWC bf16 input (hi/lo) and per-tap weights (hi/lo)
__device__ __align__(128) __nv_bfloat16 g_xt_hi[(size_t)B_*HP_*WP_*KP_];
__device__ __align__(128) __nv_bfloat16 g_xt_lo[(size_t)B_*HP_*WP_*KP_];
__device__ __align__(128) __nv_bfloat16 g_wt_hi[9*128*KP_];
__device__ __align__(128) __nv_bfloat16 g_wt_lo[9*128*KP_];

// ---------------- f32x2 helpers ----------------
__device__ __forceinline__ unsigned long long dup2(float v) {
    unsigned long long r;
    unsigned u = __float_as_uint(v);
    asm("mov.b64 %0, {%1, %1};" : "=l"(r) : "r"(u));
    return r;
}
__device__ __forceinline__ void fma2(unsigned long long& d, unsigned long long a, unsigned long long b) {
    asm("fma.rn.f32x2 %0, %1, %2, %0;" : "+l"(d) : "l"(a), "l"(b));
}
__device__ __forceinline__ float2 unpack2(unsigned long long v) {
    unsigned lo, hi;
    asm("mov.b64 {%0, %1}, %2;" : "=r"(lo), "=r"(hi) : "l"(v));
    return make_float2(__uint_as_float(lo), __uint_as_float(hi));
}

// ---------------- ptx helpers (cp.async / ldmatrix / mma.sync) ----------------
__device__ __forceinline__ uint32_t smem_u32(const void* p) {
    uint32_t a;
    asm("{ .reg .u64 t; cvta.to.shared.u64 t, %1; cvt.u32.u64 %0, t; }" : "=r"(a) : "l"(p));
    return a;
}
__device__ __forceinline__ void cp_async16(uint32_t dst, const void* src) {
    asm volatile("cp.async.cg.shared.global [%0], [%1], 16;" :: "r"(dst), "l"(src) : "memory");
}
__device__ __forceinline__ void cpa_commit() {
    asm volatile("cp.async.commit_group;" ::: "memory");
}
template<int N> __device__ __forceinline__ void cpa_wait() {
    asm volatile("cp.async.wait_group %0;" :: "n"(N) : "memory");
}
__device__ __forceinline__ void ldm_x4(uint32_t* r, uint32_t addr) {
    asm volatile("ldmatrix.sync.aligned.m8n8.x4.shared.b16 {%0,%1,%2,%3}, [%4];"
        : "=r"(r[0]), "=r"(r[1]), "=r"(r[2]), "=r"(r[3]) : "r"(addr));
}
__device__ __forceinline__ void mma_bf16(float* d, const uint32_t* a, uint32_t b0, uint32_t b1) {
    asm volatile("mma.sync.aligned.m16n8k16.row.col.f32.bf16.bf16.f32 "
        "{%0,%1,%2,%3}, {%4,%5,%6,%7}, {%8,%9}, {%0,%1,%2,%3};"
        : "+f"(d[0]), "+f"(d[1]), "+f"(d[2]), "+f"(d[3])
        : "r"(a[0]), "r"(a[1]), "r"(a[2]), "r"(a[3]), "r"(b0), "r"(b1));
}

// ---------------- 1. mean over N ----------------
__global__ void mean_kernel(const float* __restrict__ x) {
    int i = blockIdx.x * 256 + threadIdx.x;
    if (i >= B_*C_*HW_) return;
    int b = i / (C_*HW_);
    int r = i - b*(C_*HW_);
    const float* p = x + (size_t)b*N_*C_*HW_ + r;
    float s = 0.f;
#pragma unroll
    for (int n = 0; n < N_; n++) s += p[(size_t)n*C_*HW_];
    g_mean[i] = s * (1.f/N_);
}

// ---------------- 2a. GroupNorm stats ----------------
__global__ void gn_stats_kernel() {
    __shared__ double sd[256], sd2[256];
    int bg = blockIdx.x;
    const float* p = g_mean + (size_t)bg * (8*HW_);
    double s = 0.0, ss = 0.0;
    const int n4 = (8*HW_)/4;
    for (int i = threadIdx.x; i < n4; i += 256) {
        float4 v = *(const float4*)(p + (size_t)i*4);
        s  += (double)v.x + v.y + v.z + v.w;
        ss += (double)v.x*v.x + (double)v.y*v.y + (double)v.z*v.z + (double)v.w*v.w;
    }
    sd[threadIdx.x] = s; sd2[threadIdx.x] = ss;
    __syncthreads();
    for (int o = 128; o; o >>= 1) {
        if (threadIdx.x < o) { sd[threadIdx.x] += sd[threadIdx.x+o]; sd2[threadIdx.x] += sd2[threadIdx.x+o]; }
        __syncthreads();
    }
    if (threadIdx.x == 0) {
        double n = 8.0*HW_;
        double mu = sd[0]/n;
        double var = sd2[0]/n - mu*mu;
        g_stats[bg] = make_float2((float)mu, rsqrtf((float)var + 1e-5f));
    }
}

// ---------------- 2b. GroupNorm apply ----------------
__global__ void gn_apply_kernel(const float* __restrict__ gamma, const float* __restrict__ beta) {
    int i = blockIdx.x * 256 + threadIdx.x;
    if (i >= B_*C_*HW_) return;
    int b = i / (C_*HW_);
    int c = (i / HW_) % C_;
    int pix = i % HW_;
    float2 st = g_stats[b*16 + (c >> 3)];
    float v = (g_mean[i] - st.x) * st.y * gamma[c] + beta[c];
    g_lr[i] = v;
    g_lrt[((size_t)(b*HW_ + pix))*C_ + c] = v;
}

// ---------------- 3a. per-pixel L2 norm ----------------
__global__ void norm_kernel() {
    int wid = (blockIdx.x*256 + threadIdx.x) >> 5;
    int lane = threadIdx.x & 31;
    if (wid >= B_*HW_) return;
    float4 v = *(const float4*)&g_lrt[(size_t)wid*C_ + lane*4];
    float s = v.x*v.x + v.y*v.y + v.z*v.z + v.w*v.w;
#pragma unroll
    for (int o = 16; o; o >>= 1) s += __shfl_xor_sync(0xffffffffu, s, o);
    if (lane == 0) g_norm[wid] = fmaxf(sqrtf(s), 1e-8f);
}

// ---------------- 3b. cosine similarity ----------------
__global__ void sim_kernel() {
    int wid = (blockIdx.x*256 + threadIdx.x) >> 5;
    int lane = threadIdx.x & 31;
    if (wid >= B_*HW_) return;
    int b = wid / HW_;
    int pix = wid - b*HW_;
    int y = pix / W_, xx = pix - y*W_;
    float4 cv = *(const float4*)&g_lrt[(size_t)wid*C_ + lane*4];
    float inv_cn = 1.f / g_norm[wid];
    int s = 0;
#pragma unroll
    for (int i = 0; i < 7; i++) {
#pragma unroll
        for (int j = 0; j < 7; j++) {
            if (i == 3 && j == 3) continue;
            int ny = y + 2*i - 6, nx = xx + 2*j - 6;
            float sim = 0.f;
            if ((unsigned)ny < H_ && (unsigned)nx < W_) {
                int npid = b*HW_ + ny*W_ + nx;
                float4 nv = *(const float4*)&g_lrt[(size_t)npid*C_ + lane*4];
                float d = cv.x*nv.x + cv.y*nv.y + cv.z*nv.z + cv.w*nv.w;
#pragma unroll
                for (int o = 16; o; o >>= 1) d += __shfl_xor_sync(0xffffffffu, d, o);
                sim = d * inv_cn / g_norm[npid];
            }
            if (lane == 0) g_sim[((size_t)(b*NSIM_ + s)*H_ + y)*W_ + xx] = sim;
            s++;
        }
    }
}

// ---------------- 4. fused offset convs (oc padded to 64), f32x2 ----------------
__global__ void __launch_bounds__(128) offconv_kernel(
        const float* __restrict__ w0, const float* __restrict__ b0a,
        const float* __restrict__ w1, const float* __restrict__ b1a,
        const float* __restrict__ w2, const float* __restrict__ b2a) {
    __shared__ __align__(16) float s_w[9*64];
    __shared__ float s_in[6*26];
    const int tid = threadIdx.x;
    const int b = blockIdx.z;
    const int x0 = blockIdx.x * 24, y0 = blockIdx.y * 4;
    const int pxg = tid & 15, ocg = tid >> 4;
    const int px = (pxg & 3) * 6, py = pxg >> 2;
    const int oc0 = ocg * 8;
    unsigned long long acc[4][6];
#pragma unroll
    for (int p = 0; p < 4; p++)
#pragma unroll
        for (int j = 0; j < 6; j++) acc[p][j] = 0ull;

    for (int ic = 0; ic < ICOFF_; ic++) {
        __syncthreads();
        if (tid < 64) {
            const float* wp;
            if (tid < 32)      wp = w0 + ((size_t)tid*ICOFF_ + ic)*9;
            else if (tid < 48) wp = w1 + ((size_t)(tid-32)*ICOFF_ + ic)*9;
            else if (tid < 56) wp = w2 + ((size_t)(tid-48)*ICOFF_ + ic)*9;
            else               wp = nullptr;
#pragma unroll
            for (int t = 0; t < 9; t++) s_w[t*64 + tid] = wp ? wp[t] : 0.f;
        } else {
            for (int i = tid - 64; i < 156; i += 64) {
                int r = i / 26, cl = i - r*26;
                int gy = y0 + r - 1, gx = x0 + cl - 1;
                float v = 0.f;
                if ((unsigned)gy < H_ && (unsigned)gx < W_) {
                    if (ic < C_) v = g_lr[((size_t)(b*C_ + ic)*H_ + gy)*W_ + gx];
                    else         v = g_sim[((size_t)(b*NSIM_ + (ic - C_))*H_ + gy)*W_ + gx];
                }
                s_in[r*26 + cl] = v;
            }
        }
        __syncthreads();
#pragma unroll
        for (int ky = 0; ky < 3; ky++) {
            unsigned long long ind[8];
#pragma unroll
            for (int j = 0; j < 8; j++) ind[j] = dup2(s_in[(py+ky)*26 + px + j]);
#pragma unroll
            for (int kx = 0; kx < 3; kx++) {
                const int t = ky*3 + kx;
                unsigned long long wA = *(const unsigned long long*)&s_w[t*64 + oc0];
                unsigned long long wB = *(const unsigned long long*)&s_w[t*64 + oc0 + 2];
                unsigned long long wC = *(const unsigned long long*)&s_w[t*64 + oc0 + 4];
                unsigned long long wD = *(const unsigned long long*)&s_w[t*64 + oc0 + 6];
#pragma unroll
                for (int j = 0; j < 6; j++) {
                    fma2(acc[0][j], wA, ind[kx+j]);
                    fma2(acc[1][j], wB, ind[kx+j]);
                    fma2(acc[2][j], wC, ind[kx+j]);
                    fma2(acc[3][j], wD, ind[kx+j]);
                }
            }
        }
    }
    int oy = y0 + py;
#pragma unroll
    for (int p = 0; p < 4; p++) {
        int oc = oc0 + 2*p;
        if (oc >= OCOFF_) continue;
        float bb0 = (oc   < 32) ? b0a[oc]   : (oc   < 48 ? b1a[oc-32]   : b2a[oc-48]);
        float bb1 = (oc+1 < 32) ? b0a[oc+1] : (oc+1 < 48 ? b1a[oc-31] : b2a[oc-47]);
        float* o0 = g_off + ((size_t)(b*OCOFF_ + oc)*H_ + oy)*W_ + x0 + px;
        float* o1 = o0 + HW_;
#pragma unroll
        for (int j = 0; j < 6; j++) {
            float2 v = unpack2(acc[p][j]);
            o0[j] = v.x + bb0;
            o1[j] = v.y + bb1;
        }
    }
}

// ---------------- 5a. targeted zero-fill (pad-k columns, all pixels) ----------------
__global__ void zfill_padk_kernel() {
    // zero k in [896,960) (128B = 8 x uint4) for every padded pixel, both bufs
    int i = blockIdx.x * 256 + threadIdx.x;
    const int total = B_*HP_*WP_ * 16;   // px * 8 chunks * 2 bufs
    if (i >= total) return;
    int px = i >> 4;
    int rest = i & 15;
    int buf = rest >> 3, ch = rest & 7;
    char* base = (char*)(buf ? g_xt_lo : g_xt_hi) + (size_t)px*(KP_*2) + 1792 + ch*16;
    *(uint4*)base = make_uint4(0u,0u,0u,0u);
}

// ---------------- 5b. targeted zero-fill (border pixels, full K) ----------------
__global__ void zfill_border_kernel() {
    // pixels NOT written by pack_x: y==0 || y==121 || x==0 || x>=361
    int i = blockIdx.x * 256 + threadIdx.x;
    const int total = B_ * 2184 * 120 * 2;   // b * border_px * (1920B/16) * bufs
    if (i >= total) return;
    int ch = i % 120;
    int r = i / 120;
    int buf = r & 1; r >>= 1;
    int p = r % 2184;
    int b = r / 2184;
    int y, x;
    if (p < 744) { y = (p < 372) ? 0 : 121; x = p % 372; }
    else {
        int q = p - 744;            // 0..1439 = 120 y-rows x 12 x-cols
        y = 1 + q / 12;
        int m = q % 12;
        x = (m == 0) ? 0 : (360 + m);   // x=0 or x=361..371
    }
    char* base = (char*)(buf ? g_xt_lo : g_xt_hi)
               + (((size_t)b*HP_ + y)*WP_ + x)*(KP_*2) + ch*16;
    *(uint4*)base = make_uint4(0u,0u,0u,0u);
}

// ---------------- 5c. pack x (NCHW fp32 -> padded NHWC bf16 hi/lo) ----------------
__global__ void pack_x_kernel(const float* __restrict__ x) {
    __shared__ float t[32][33];
    int b  = blockIdx.z;
    int cg = blockIdx.y;           // 28 groups of 32 channels
    int pg = blockIdx.x;           // 1350 groups of 32 pixels
    int tx = threadIdx.x & 31, ty = threadIdx.x >> 5;   // 256 threads
    int pix0 = pg * 32;
    const float* src = x + ((size_t)b*896 + cg*32)*HW_ + pix0;
#pragma unroll
    for (int k = 0; k < 4; k++)
        t[ty + 8*k][tx] = src[(size_t)(ty + 8*k)*HW_ + tx];
    __syncthreads();
#pragma unroll
    for (int k = 0; k < 4; k++) {
        int p = pix0 + ty + 8*k;
        int yy = p / W_, xx = p - yy*W_;
        size_t ro = (((size_t)b*HP_ + yy + 1)*WP_ + (xx + 1))*KP_ + cg*32;
        float v = t[tx][ty + 8*k];
        __nv_bfloat16 h = __float2bfloat16(v);
        __nv_bfloat16 l = __float2bfloat16(v - __bfloat162float(h));
        g_xt_hi[ro + tx] = h;
        g_xt_lo[ro + tx] = l;
    }
}

// ---------------- 5d. coord channels (k=896 gx, k=897 gy) ----------------
__global__ void pack_coord_kernel() {
    int i = blockIdx.x * 256 + threadIdx.x;
    if (i >= B_*HW_) return;
    int b = i / HW_, p = i - b*HW_;
    int yy = p / W_, xx = p - yy*W_;
    size_t ro = (((size_t)b*HP_ + yy + 1)*WP_ + (xx + 1))*KP_;
    float gx = xx*(2.f/(W_-1)) - 1.f;
    float gy = yy*(2.f/(H_-1)) - 1.f;
    __nv_bfloat16 hx = __float2bfloat16(gx);
    __nv_bfloat16 hy = __float2bfloat16(gy);
    g_xt_hi[ro + 896] = hx;
    g_xt_lo[ro + 896] = __float2bfloat16(gx - __bfloat162float(hx));
    g_xt_hi[ro + 897] = hy;
    g_xt_lo[ro + 897] = __float2bfloat16(gy - __bfloat162float(hy));
}

// ---------------- 5e. pack weights (per tap, K-major, hi/lo) ----------------
__global__ void pack_w_kernel(const float* __restrict__ w) {
    int i = blockIdx.x * 256 + threadIdx.x;
    if (i >= 9*128*KP_) return;
    int tap = i / (128*KP_);
    int r = i - tap*(128*KP_);
    int oc = r / KP_, k = r - oc*KP_;
    float v = (k < 898) ? w[((size_t)oc*898 + k)*9 + tap] : 0.f;
    __nv_bfloat16 h = __float2bfloat16(v);
    g_wt_hi[i] = h;
    g_wt_lo[i] = __float2bfloat16(v - __bfloat162float(h));
}

// ---------------- 5f. conv1: mma.sync bf16, A-reuse across kx + shared-B dual pass ----------------
// per CTA (256 thr): M=128 px (one y row, x-tile of 120+halo), N=128 oc.
// groups g=(kc,ky): load A_hi/A_lo once (130 rows), then 6 B-stages:
//   s=0..2: B=Bhi(ky,kx=s):  acc += Ah*Bh  and  acc += Al*Bh   (128 HMMA/warp)
//   s=3..5: B=Blo(ky,kx=s-3): acc += Ah*Bl                      (64 HMMA/warp)
extern __shared__ char conv_smem[];

__global__ void __launch_bounds__(256, 2) conv1_mma_kernel(const float* __restrict__ bias) {
    const uint32_t sb = smem_u32(conv_smem);
    const int tid = threadIdx.x;
    const int b = blockIdx.z, y = blockIdx.y, x0 = blockIdx.x * 120;
    const int warp = tid >> 5, lane = tid & 31;
    const int m0 = (warp >> 1) * 32, n0 = (warp & 1) * 64;   // 4x2 warp grid

    float acc[2][8][4];
#pragma unroll
    for (int mt = 0; mt < 2; mt++)
#pragma unroll
        for (int nt = 0; nt < 8; nt++)
#pragma unroll
            for (int e = 0; e < 4; e++) acc[mt][nt][e] = 0.f;

    const int lrow = tid >> 1, cb = (tid & 1) * 4;

    // issue A tile: 130 rows x 128B from px rows x0..x0+129 of padded row (y+ky), chunk kc
    auto issueA = [&](int g, bool lo, uint32_t dstBase) {
        int ky = g % 3, kc = g / 3;
        const __nv_bfloat16* base = lo ? g_xt_lo : g_xt_hi;
        const char* src0 = (const char*)(base + (((size_t)b*HP_ + y + ky)*WP_ + x0)*KP_ + kc*64);
        {
            const char* s = src0 + (size_t)lrow * (KP_*2);
            uint32_t d = dstBase + (uint32_t)lrow * 128;
#pragma unroll
            for (int t = 0; t < 4; t++) {
                int c = cb + t;
                cp_async16(d + (uint32_t)((c ^ (lrow & 7)) << 4), s + c*16);
            }
        }
        if (tid < 4) {
            int r2 = 128 + (tid >> 1);
            int cb2 = (tid & 1) * 4;
            const char* s = src0 + (size_t)r2 * (KP_*2);
            uint32_t d = dstBase + (uint32_t)r2 * 128;
#pragma unroll
            for (int t = 0; t < 4; t++) {
                int c = cb2 + t;
                cp_async16(d + (uint32_t)((c ^ (r2 & 7)) << 4), s + c*16);
            }
        }
    };

    // issue B tile for stage t: 128 oc rows x 128B
    auto issueB = [&](int t) {
        int g = t / 6, s = t - g*6;
        int ky = g % 3, kc = g / 3;
        int kx = (s < 3) ? s : s - 3;
        const __nv_bfloat16* base = (s < 3) ? g_wt_hi : g_wt_lo;
        const char* src = (const char*)(base + ((size_t)(ky*3 + kx)*128 + lrow)*KP_ + kc*64);
        uint32_t d = sb + 3*ASZ_ + (uint32_t)(t % 3)*BSZ_ + (uint32_t)lrow * 128;
#pragma unroll
        for (int tt = 0; tt < 4; tt++) {
            int c = cb + tt;
            cp_async16(d + (uint32_t)((c ^ (lrow & 7)) << 4), src + c*16);
        }
    };

    // prologue
    issueA(0, false, sb + 0);          // Ahi buf0
    issueA(0, true,  sb + 2*ASZ_);     // Alo
    issueB(0);
    cpa_commit();
    issueB(1);
    cpa_commit();

    const int gq = lane >> 3, rq = lane & 7;
    for (int t = 0; t < NSTG1_; t++) {
        int g = t / 6, s = t - g*6;
        if (s == 0 && g + 1 < NGRP_) issueA(g + 1, false, sb + (uint32_t)((g + 1) & 1)*ASZ_);
        if (s == 3 && g + 1 < NGRP_) issueA(g + 1, true,  sb + 2*ASZ_);
        if (t + 2 < NSTG1_) issueB(t + 2);
        cpa_commit();
        cpa_wait<2>();
        __syncthreads();

        const uint32_t Ahi = sb + (uint32_t)(g & 1)*ASZ_;
        const uint32_t Alo = sb + 2*ASZ_;
        const uint32_t Bs  = sb + 3*ASZ_ + (uint32_t)(t % 3)*BSZ_;
        const bool dual = (s < 3);
        const int kx = dual ? s : s - 3;

#pragma unroll
        for (int kt = 0; kt < 4; kt++) {
            const int c = kt*2 + (gq >> 1);
            uint32_t ah[2][4], al[2][4];
#pragma unroll
            for (int mt = 0; mt < 2; mt++) {
                int sr = m0 + mt*16 + ((gq & 1) << 3) + rq + kx;
                uint32_t off = (uint32_t)sr*128 + (uint32_t)((c ^ (sr & 7)) << 4);
                ldm_x4(ah[mt], Ahi + off);
                if (dual) ldm_x4(al[mt], Alo + off);
            }
#pragma unroll
            for (int nt = 0; nt < 4; nt++) {
                uint32_t bq[4];
                int brow = n0 + nt*16 + ((gq & 1) << 3) + rq;
                ldm_x4(bq, Bs + (uint32_t)brow*128 + (uint32_t)((c ^ (brow & 7)) << 4));
#pragma unroll
                for (int mt = 0; mt < 2; mt++) {
                    mma_bf16(acc[mt][nt*2],     ah[mt], bq[0], bq[2]);
                    mma_bf16(acc[mt][nt*2 + 1], ah[mt], bq[1], bq[3]);
                }
                if (dual) {
#pragma unroll
                    for (int mt = 0; mt < 2; mt++) {
                        mma_bf16(acc[mt][nt*2],     al[mt], bq[0], bq[2]);
                        mma_bf16(acc[mt][nt*2 + 1], al[mt], bq[1], bq[3]);
                    }
                }
            }
        }
        __syncthreads();
    }

    // epilogue: bias + relu -> NCHW g_feat
    const int qr = lane >> 2, qc = (lane & 3) * 2;
#pragma unroll
    for (int mt = 0; mt < 2; mt++) {
        int lm = m0 + mt*16 + qr;
#pragma unroll
        for (int nt = 0; nt < 8; nt++) {
            int oc = n0 + nt*8 + qc;
            float b0v = __ldg(bias + oc), b1v = __ldg(bias + oc + 1);
            float* p = g_feat + ((size_t)b*HID_ + oc)*HW_ + y*W_ + x0;
            if (lm < 120) {
                p[lm]       = fmaxf(acc[mt][nt][0] + b0v, 0.f);
                p[lm + HW_] = fmaxf(acc[mt][nt][1] + b1v, 0.f);
            }
            if (lm + 8 < 120) {
                p[lm + 8]       = fmaxf(acc[mt][nt][2] + b0v, 0.f);
                p[lm + 8 + HW_] = fmaxf(acc[mt][nt][3] + b1v, 0.f);
            }
        }
    }
}

// ---------------- 6. fused triple deformable sampling + average ----------------
__device__ __forceinline__ float bilin(const float* __restrict__ f, float ix, float iy) {
    float fx = floorf(ix), fy = floorf(iy);
    float wx = ix - fx, wy = iy - fy;
    int xl = (int)fx, yl = (int)fy;
    int x0i = min(max(xl,     0), W_-1);
    int x1i = min(max(xl + 1, 0), W_-1);
    int y0i = min(max(yl,     0), H_-1);
    int y1i = min(max(yl + 1, 0), H_-1);
    float v00 = f[y0i*W_ + x0i], v01 = f[y0i*W_ + x1i];
    float v10 = f[y1i*W_ + x0i], v11 = f[y1i*W_ + x1i];
    return (v00*(1.f-wx) + v01*wx)*(1.f-wy) + (v10*(1.f-wx) + v11*wx)*wy;
}

__global__ void sample_kernel(float* __restrict__ out) {
    int i = blockIdx.x * 256 + threadIdx.x;
    if (i >= B_*C_*HW_) return;
    int xx = i % W_;
    int y  = (i / W_) % H_;
    int c  = (i / HW_) % C_;
    int b  = i / (C_*HW_);
    const float* offp = g_off + (size_t)b*OCOFF_*HW_ + y*W_ + xx;
    float ox0 = offp[(size_t)( 0 + (c>>3))*HW_], oy0 = offp[(size_t)(16 + (c>>3))*HW_];
    float ox1 = offp[(size_t)(32 + (c>>4))*HW_], oy1 = offp[(size_t)(40 + (c>>4))*HW_];
    float ox2 = offp[(size_t)(48 + (c>>5))*HW_], oy2 = offp[(size_t)(52 + (c>>5))*HW_];
    const float* f = g_feat + (size_t)(b*HID_ + c)*HW_;
    float s = bilin(f, xx + ox0, y + oy0)
            + bilin(f, xx + ox1, y + oy1)
            + bilin(f, xx + ox2, y + oy2);
    out[i] = s * (1.f/3.f);
}

// ---------------- launch ----------------
extern "C" void kernel_launch(void* const* d_in, const int* in_sizes, int n_in,
                              void* d_out, int out_size) {
    const float* x        = (const float*)d_in[0];
    const float* conv_w   = (const float*)d_in[1];
    const float* conv_b   = (const float*)d_in[2];
    const float* gn_gamma = (const float*)d_in[3];
    const float* gn_beta  = (const float*)d_in[4];
    const float* off_w    = (const float*)d_in[5];
    const float* off_b    = (const float*)d_in[6];
    const float* off1_w   = (const float*)d_in[7];
    const float* off1_b   = (const float*)d_in[8];
    const float* off2_w   = (const float*)d_in[9];
    const float* off2_b   = (const float*)d_in[10];
    float* out = (float*)d_out;

    static bool attr_done = false;
    if (!attr_done) {
        cudaFuncSetAttribute(conv1_mma_kernel, cudaFuncAttributeMaxDynamicSharedMemorySize, SMEM_CONV_);
        attr_done = true;
    }

    const int total = B_*C_*HW_;

    // pack path for mma conv1 (targeted zero-fill, then pack)
    zfill_padk_kernel<<<(B_*HP_*WP_*16 + 255)/256, 256>>>();
    zfill_border_kernel<<<(B_*2184*120*2 + 255)/256, 256>>>();
    pack_x_kernel<<<dim3(HW_/32, 28, B_), 256>>>(x);
    pack_coord_kernel<<<(B_*HW_ + 255)/256, 256>>>();
    pack_w_kernel<<<(9*128*KP_ + 255)/256, 256>>>(conv_w);

    mean_kernel<<<(total + 255)/256, 256>>>(x);
    gn_stats_kernel<<<32, 256>>>();
    gn_apply_kernel<<<(total + 255)/256, 256>>>(gn_gamma, gn_beta);
    norm_kernel<<<(B_*HW_ + 7)/8, 256>>>();
    sim_kernel<<<(B_*HW_ + 7)/8, 256>>>();
    offconv_kernel<<<dim3(15, 30, B_), 128>>>(off_w, off_b, off1_w, off1_b, off2_w, off2_b);
    conv1_mma_kernel<<<dim3(3, 120, B_), 256, SMEM_CONV_>>>(conv_b);
    sample_kernel<<<(total + 255)/256, 256>>>(out);
}

// round 9
// speedup vs baseline: 2.4876x; 1.3283x over previous
#include <cuda_runtime.h>
#include <cuda_bf16.h>
#include <cuda_fp16.h>
#include <cstdint>

#define B_ 2
#define N_ 7
#define C_ 128
#define H_ 120
#define W_ 360
#define HW_ (H_*W_)
#define HID_ 128
#define NSIM_ 48
#define OCOFF_ 56
#define ICOFF_ 176

// conv1 mma geometry (fp16 2-term split: A=Ah+Al fp16, B single fp16)
#define KP_ 960                    // padded K (898 -> 960, 15 chunks of 64)
#define HP_ 122
#define WP_ 372
#define ASZ_ 16640                 // A tile: 130 rows x 128B
#define BSZ_ 16384                 // B tile: 128 rows x 128B
#define NGRP_ 45                   // 15 kc x 3 ky
#define NSTG_ 135                  // 45 groups x 3 kx stages
#define SMEM_CONV_ (4*ASZ_ + 2*BSZ_)   // Ahi x2, Alo x2, B x2 = 99328B -> occ 2

// ---------------- scratch (device globals; no runtime alloc) ----------------
__device__ float g_mean[B_*C_*HW_];
__device__ float g_lr  [B_*C_*HW_];
__device__ float g_lrt [(size_t)B_*HW_*C_];
__device__ float g_norm[B_*HW_];
__device__ float g_sim [B_*NSIM_*HW_];
__device__ float g_feat[B_*HID_*HW_];
__device__ float g_off [B_*OCOFF_*HW_];
__device__ float2 g_stats[32];
// padded NHWC fp16 input (hi/lo) and per-tap fp16 weights
__device__ __align__(128) __half g_xt_hi[(size_t)B_*HP_*WP_*KP_];
__device__ __align__(128) __half g_xt_lo[(size_t)B_*HP_*WP_*KP_];
__device__ __align__(128) __half g_wt[9*128*KP_];

// ---------------- f32x2 helpers ----------------
__device__ __forceinline__ unsigned long long dup2(float v) {
    unsigned long long r;
    unsigned u = __float_as_uint(v);
    asm("mov.b64 %0, {%1, %1};" : "=l"(r) : "r"(u));
    return r;
}
__device__ __forceinline__ void fma2(unsigned long long& d, unsigned long long a, unsigned long long b) {
    asm("fma.rn.f32x2 %0, %1, %2, %0;" : "+l"(d) : "l"(a), "l"(b));
}
__device__ __forceinline__ float2 unpack2(unsigned long long v) {
    unsigned lo, hi;
    asm("mov.b64 {%0, %1}, %2;" : "=r"(lo), "=r"(hi) : "l"(v));
    return make_float2(__uint_as_float(lo), __uint_as_float(hi));
}

// ---------------- ptx helpers (cp.async / ldmatrix / mma.sync) ----------------
__device__ __forceinline__ uint32_t smem_u32(const void* p) {
    uint32_t a;
    asm("{ .reg .u64 t; cvta.to.shared.u64 t, %1; cvt.u32.u64 %0, t; }" : "=r"(a) : "l"(p));
    return a;
}
__device__ __forceinline__ void cp_async16(uint32_t dst, const void* src) {
    asm volatile("cp.async.cg.shared.global [%0], [%1], 16;" :: "r"(dst), "l"(src) : "memory");
}
__device__ __forceinline__ void cpa_commit() {
    asm volatile("cp.async.commit_group;" ::: "memory");
}
template<int N> __device__ __forceinline__ void cpa_wait() {
    asm volatile("cp.async.wait_group %0;" :: "n"(N) : "memory");
}
__device__ __forceinline__ void ldm_x4(uint32_t* r, uint32_t addr) {
    asm volatile("ldmatrix.sync.aligned.m8n8.x4.shared.b16 {%0,%1,%2,%3}, [%4];"
        : "=r"(r[0]), "=r"(r[1]), "=r"(r[2]), "=r"(r[3]) : "r"(addr));
}
__device__ __forceinline__ void mma_f16(float* d, const uint32_t* a, uint32_t b0, uint32_t b1) {
    asm volatile("mma.sync.aligned.m16n8k16.row.col.f32.f16.f16.f32 "
        "{%0,%1,%2,%3}, {%4,%5,%6,%7}, {%8,%9}, {%0,%1,%2,%3};"
        : "+f"(d[0]), "+f"(d[1]), "+f"(d[2]), "+f"(d[3])
        : "r"(a[0]), "r"(a[1]), "r"(a[2]), "r"(a[3]), "r"(b0), "r"(b1));
}

// ---------------- 1. mean over N ----------------
__global__ void mean_kernel(const float* __restrict__ x) {
    int i = blockIdx.x * 256 + threadIdx.x;
    if (i >= B_*C_*HW_) return;
    int b = i / (C_*HW_);
    int r = i - b*(C_*HW_);
    const float* p = x + (size_t)b*N_*C_*HW_ + r;
    float s = 0.f;
#pragma unroll
    for (int n = 0; n < N_; n++) s += p[(size_t)n*C_*HW_];
    g_mean[i] = s * (1.f/N_);
}

// ---------------- 2a. GroupNorm stats ----------------
__global__ void gn_stats_kernel() {
    __shared__ double sd[256], sd2[256];
    int bg = blockIdx.x;
    const float* p = g_mean + (size_t)bg * (8*HW_);
    double s = 0.0, ss = 0.0;
    const int n4 = (8*HW_)/4;
    for (int i = threadIdx.x; i < n4; i += 256) {
        float4 v = *(const float4*)(p + (size_t)i*4);
        s  += (double)v.x + v.y + v.z + v.w;
        ss += (double)v.x*v.x + (double)v.y*v.y + (double)v.z*v.z + (double)v.w*v.w;
    }
    sd[threadIdx.x] = s; sd2[threadIdx.x] = ss;
    __syncthreads();
    for (int o = 128; o; o >>= 1) {
        if (threadIdx.x < o) { sd[threadIdx.x] += sd[threadIdx.x+o]; sd2[threadIdx.x] += sd2[threadIdx.x+o]; }
        __syncthreads();
    }
    if (threadIdx.x == 0) {
        double n = 8.0*HW_;
        double mu = sd[0]/n;
        double var = sd2[0]/n - mu*mu;
        g_stats[bg] = make_float2((float)mu, rsqrtf((float)var + 1e-5f));
    }
}

// ---------------- 2b. GroupNorm apply ----------------
__global__ void gn_apply_kernel(const float* __restrict__ gamma, const float* __restrict__ beta) {
    int i = blockIdx.x * 256 + threadIdx.x;
    if (i >= B_*C_*HW_) return;
    int b = i / (C_*HW_);
    int c = (i / HW_) % C_;
    int pix = i % HW_;
    float2 st = g_stats[b*16 + (c >> 3)];
    float v = (g_mean[i] - st.x) * st.y * gamma[c] + beta[c];
    g_lr[i] = v;
    g_lrt[((size_t)(b*HW_ + pix))*C_ + c] = v;
}

// ---------------- 3a. per-pixel L2 norm ----------------
__global__ void norm_kernel() {
    int wid = (blockIdx.x*256 + threadIdx.x) >> 5;
    int lane = threadIdx.x & 31;
    if (wid >= B_*HW_) return;
    float4 v = *(const float4*)&g_lrt[(size_t)wid*C_ + lane*4];
    float s = v.x*v.x + v.y*v.y + v.z*v.z + v.w*v.w;
#pragma unroll
    for (int o = 16; o; o >>= 1) s += __shfl_xor_sync(0xffffffffu, s, o);
    if (lane == 0) g_norm[wid] = fmaxf(sqrtf(s), 1e-8f);
}

// ---------------- 3b. cosine similarity ----------------
__global__ void sim_kernel() {
    int wid = (blockIdx.x*256 + threadIdx.x) >> 5;
    int lane = threadIdx.x & 31;
    if (wid >= B_*HW_) return;
    int b = wid / HW_;
    int pix = wid - b*HW_;
    int y = pix / W_, xx = pix - y*W_;
    float4 cv = *(const float4*)&g_lrt[(size_t)wid*C_ + lane*4];
    float inv_cn = 1.f / g_norm[wid];
    int s = 0;
#pragma unroll
    for (int i = 0; i < 7; i++) {
#pragma unroll
        for (int j = 0; j < 7; j++) {
            if (i == 3 && j == 3) continue;
            int ny = y + 2*i - 6, nx = xx + 2*j - 6;
            float sim = 0.f;
            if ((unsigned)ny < H_ && (unsigned)nx < W_) {
                int npid = b*HW_ + ny*W_ + nx;
                float4 nv = *(const float4*)&g_lrt[(size_t)npid*C_ + lane*4];
                float d = cv.x*nv.x + cv.y*nv.y + cv.z*nv.z + cv.w*nv.w;
#pragma unroll
                for (int o = 16; o; o >>= 1) d += __shfl_xor_sync(0xffffffffu, d, o);
                sim = d * inv_cn / g_norm[npid];
            }
            if (lane == 0) g_sim[((size_t)(b*NSIM_ + s)*H_ + y)*W_ + xx] = sim;
            s++;
        }
    }
}

// ---------------- 4. fused offset convs (oc padded to 64), f32x2 ----------------
__global__ void __launch_bounds__(128) offconv_kernel(
        const float* __restrict__ w0, const float* __restrict__ b0a,
        const float* __restrict__ w1, const float* __restrict__ b1a,
        const float* __restrict__ w2, const float* __restrict__ b2a) {
    __shared__ __align__(16) float s_w[9*64];
    __shared__ float s_in[6*26];
    const int tid = threadIdx.x;
    const int b = blockIdx.z;
    const int x0 = blockIdx.x * 24, y0 = blockIdx.y * 4;
    const int pxg = tid & 15, ocg = tid >> 4;
    const int px = (pxg & 3) * 6, py = pxg >> 2;
    const int oc0 = ocg * 8;
    unsigned long long acc[4][6];
#pragma unroll
    for (int p = 0; p < 4; p++)
#pragma unroll
        for (int j = 0; j < 6; j++) acc[p][j] = 0ull;

    for (int ic = 0; ic < ICOFF_; ic++) {
        __syncthreads();
        if (tid < 64) {
            const float* wp;
            if (tid < 32)      wp = w0 + ((size_t)tid*ICOFF_ + ic)*9;
            else if (tid < 48) wp = w1 + ((size_t)(tid-32)*ICOFF_ + ic)*9;
            else if (tid < 56) wp = w2 + ((size_t)(tid-48)*ICOFF_ + ic)*9;
            else               wp = nullptr;
#pragma unroll
            for (int t = 0; t < 9; t++) s_w[t*64 + tid] = wp ? wp[t] : 0.f;
        } else {
            for (int i = tid - 64; i < 156; i += 64) {
                int r = i / 26, cl = i - r*26;
                int gy = y0 + r - 1, gx = x0 + cl - 1;
                float v = 0.f;
                if ((unsigned)gy < H_ && (unsigned)gx < W_) {
                    if (ic < C_) v = g_lr[((size_t)(b*C_ + ic)*H_ + gy)*W_ + gx];
                    else         v = g_sim[((size_t)(b*NSIM_ + (ic - C_))*H_ + gy)*W_ + gx];
                }
                s_in[r*26 + cl] = v;
            }
        }
        __syncthreads();
#pragma unroll
        for (int ky = 0; ky < 3; ky++) {
            unsigned long long ind[8];
#pragma unroll
            for (int j = 0; j < 8; j++) ind[j] = dup2(s_in[(py+ky)*26 + px + j]);
#pragma unroll
            for (int kx = 0; kx < 3; kx++) {
                const int t = ky*3 + kx;
                unsigned long long wA = *(const unsigned long long*)&s_w[t*64 + oc0];
                unsigned long long wB = *(const unsigned long long*)&s_w[t*64 + oc0 + 2];
                unsigned long long wC = *(const unsigned long long*)&s_w[t*64 + oc0 + 4];
                unsigned long long wD = *(const unsigned long long*)&s_w[t*64 + oc0 + 6];
#pragma unroll
                for (int j = 0; j < 6; j++) {
                    fma2(acc[0][j], wA, ind[kx+j]);
                    fma2(acc[1][j], wB, ind[kx+j]);
                    fma2(acc[2][j], wC, ind[kx+j]);
                    fma2(acc[3][j], wD, ind[kx+j]);
                }
            }
        }
    }
    int oy = y0 + py;
#pragma unroll
    for (int p = 0; p < 4; p++) {
        int oc = oc0 + 2*p;
        if (oc >= OCOFF_) continue;
        float bb0 = (oc   < 32) ? b0a[oc]   : (oc   < 48 ? b1a[oc-32]   : b2a[oc-48]);
        float bb1 = (oc+1 < 32) ? b0a[oc+1] : (oc+1 < 48 ? b1a[oc-31] : b2a[oc-47]);
        float* o0 = g_off + ((size_t)(b*OCOFF_ + oc)*H_ + oy)*W_ + x0 + px;
        float* o1 = o0 + HW_;
#pragma unroll
        for (int j = 0; j < 6; j++) {
            float2 v = unpack2(acc[p][j]);
            o0[j] = v.x + bb0;
            o1[j] = v.y + bb1;
        }
    }
}

// ---------------- 5a. targeted zero-fill (pad-k columns, all pixels) ----------------
__global__ void zfill_padk_kernel() {
    int i = blockIdx.x * 256 + threadIdx.x;
    const int total = B_*HP_*WP_ * 16;   // px * 8 chunks * 2 bufs
    if (i >= total) return;
    int px = i >> 4;
    int rest = i & 15;
    int buf = rest >> 3, ch = rest & 7;
    char* base = (char*)(buf ? g_xt_lo : g_xt_hi) + (size_t)px*(KP_*2) + 1792 + ch*16;
    *(uint4*)base = make_uint4(0u,0u,0u,0u);
}

// ---------------- 5b. targeted zero-fill (border pixels, full K) ----------------
__global__ void zfill_border_kernel() {
    int i = blockIdx.x * 256 + threadIdx.x;
    const int total = B_ * 2184 * 120 * 2;
    if (i >= total) return;
    int ch = i % 120;
    int r = i / 120;
    int buf = r & 1; r >>= 1;
    int p = r % 2184;
    int b = r / 2184;
    int y, x;
    if (p < 744) { y = (p < 372) ? 0 : 121; x = p % 372; }
    else {
        int q = p - 744;
        y = 1 + q / 12;
        int m = q % 12;
        x = (m == 0) ? 0 : (360 + m);
    }
    char* base = (char*)(buf ? g_xt_lo : g_xt_hi)
               + (((size_t)b*HP_ + y)*WP_ + x)*(KP_*2) + ch*16;
    *(uint4*)base = make_uint4(0u,0u,0u,0u);
}

// ---------------- 5c. pack x (NCHW fp32 -> padded NHWC fp16 hi/lo) ----------------
__global__ void pack_x_kernel(const float* __restrict__ x) {
    __shared__ float t[32][33];
    int b  = blockIdx.z;
    int cg = blockIdx.y;
    int pg = blockIdx.x;
    int tx = threadIdx.x & 31, ty = threadIdx.x >> 5;
    int pix0 = pg * 32;
    const float* src = x + ((size_t)b*896 + cg*32)*HW_ + pix0;
#pragma unroll
    for (int k = 0; k < 4; k++)
        t[ty + 8*k][tx] = src[(size_t)(ty + 8*k)*HW_ + tx];
    __syncthreads();
#pragma unroll
    for (int k = 0; k < 4; k++) {
        int p = pix0 + ty + 8*k;
        int yy = p / W_, xx = p - yy*W_;
        size_t ro = (((size_t)b*HP_ + yy + 1)*WP_ + (xx + 1))*KP_ + cg*32;
        float v = t[tx][ty + 8*k];
        __half h = __float2half(v);
        __half l = __float2half(v - __half2float(h));
        g_xt_hi[ro + tx] = h;
        g_xt_lo[ro + tx] = l;
    }
}

// ---------------- 5d. coord channels (k=896 gx, k=897 gy) ----------------
__global__ void pack_coord_kernel() {
    int i = blockIdx.x * 256 + threadIdx.x;
    if (i >= B_*HW_) return;
    int b = i / HW_, p = i - b*HW_;
    int yy = p / W_, xx = p - yy*W_;
    size_t ro = (((size_t)b*HP_ + yy + 1)*WP_ + (xx + 1))*KP_;
    float gx = xx*(2.f/(W_-1)) - 1.f;
    float gy = yy*(2.f/(H_-1)) - 1.f;
    __half hx = __float2half(gx);
    __half hy = __float2half(gy);
    g_xt_hi[ro + 896] = hx;
    g_xt_lo[ro + 896] = __float2half(gx - __half2float(hx));
    g_xt_hi[ro + 897] = hy;
    g_xt_lo[ro + 897] = __float2half(gy - __half2float(hy));
}

// ---------------- 5e. pack weights (per tap, K-major, fp16) ----------------
__global__ void pack_w_kernel(const float* __restrict__ w) {
    int i = blockIdx.x * 256 + threadIdx.x;
    if (i >= 9*128*KP_) return;
    int tap = i / (128*KP_);
    int r = i - tap*(128*KP_);
    int oc = r / KP_, k = r - oc*KP_;
    float v = (k < 898) ? w[((size_t)oc*898 + k)*9 + tap] : 0.f;
    g_wt[i] = __float2half(v);
}

// ---------------- 5f. conv1: mma.sync fp16 2-term split, A-reuse across kx ----------------
// per CTA (256 thr): M=128 px (one y row, x-tile of 120+halo), N=128 oc.
// groups g=(kc,ky): load Ah+Al once (130 rows each); 3 B-stages (kx=0,1,2),
// each stage computes acc += Ah*B + Al*B (128 HMMA/warp).
extern __shared__ char conv_smem[];

__global__ void __launch_bounds__(256, 2) conv1_mma_kernel(const float* __restrict__ bias) {
    const uint32_t sb = smem_u32(conv_smem);
    const int tid = threadIdx.x;
    const int b = blockIdx.z, y = blockIdx.y, x0 = blockIdx.x * 120;
    const int warp = tid >> 5, lane = tid & 31;
    const int m0 = (warp >> 1) * 32, n0 = (warp & 1) * 64;   // 4x2 warp grid

    float acc[2][8][4];
#pragma unroll
    for (int mt = 0; mt < 2; mt++)
#pragma unroll
        for (int nt = 0; nt < 8; nt++)
#pragma unroll
            for (int e = 0; e < 4; e++) acc[mt][nt][e] = 0.f;

    const int lrow = tid >> 1, cb = (tid & 1) * 4;

    // buffers: Ahi[i]=sb+i*ASZ, Alo[i]=sb+(2+i)*ASZ, B[i]=sb+4*ASZ+i*BSZ
    auto issueA = [&](int g, bool lo, int bufi) {
        int ky = g % 3, kc = g / 3;
        const __half* base = lo ? g_xt_lo : g_xt_hi;
        const char* src0 = (const char*)(base + (((size_t)b*HP_ + y + ky)*WP_ + x0)*KP_ + kc*64);
        uint32_t dstBase = sb + (uint32_t)((lo ? 2 : 0) + bufi)*ASZ_;
        {
            const char* s = src0 + (size_t)lrow * (KP_*2);
            uint32_t d = dstBase + (uint32_t)lrow * 128;
#pragma unroll
            for (int t = 0; t < 4; t++) {
                int c = cb + t;
                cp_async16(d + (uint32_t)((c ^ (lrow & 7)) << 4), s + c*16);
            }
        }
        if (tid < 4) {
            int r2 = 128 + (tid >> 1);
            int cb2 = (tid & 1) * 4;
            const char* s = src0 + (size_t)r2 * (KP_*2);
            uint32_t d = dstBase + (uint32_t)r2 * 128;
#pragma unroll
            for (int t = 0; t < 4; t++) {
                int c = cb2 + t;
                cp_async16(d + (uint32_t)((c ^ (r2 & 7)) << 4), s + c*16);
            }
        }
    };

    auto issueB = [&](int t) {
        int g = t / 3, s = t - g*3;     // s = kx
        int ky = g % 3, kc = g / 3;
        const char* src = (const char*)(g_wt + ((size_t)(ky*3 + s)*128 + lrow)*KP_ + kc*64);
        uint32_t d = sb + 4*ASZ_ + (uint32_t)(t & 1)*BSZ_ + (uint32_t)lrow * 128;
#pragma unroll
        for (int tt = 0; tt < 4; tt++) {
            int c = cb + tt;
            cp_async16(d + (uint32_t)((c ^ (lrow & 7)) << 4), src + c*16);
        }
    };

    // prologue: stage 0's A and B
    issueA(0, false, 0);
    issueA(0, true,  0);
    issueB(0);
    cpa_commit();

    const int gq = lane >> 3, rq = lane & 7;
    for (int t = 0; t < NSTG_; t++) {
        const int g = t / 3, s = t - g*3;
        cpa_wait<0>();
        __syncthreads();
        // issue next stage (writes opposite-parity buffers; reads of this stage are
        // protected because all warps passed the barrier after finishing stage t-1)
        if (s == 0 && g + 1 < NGRP_) {
            issueA(g + 1, false, (g + 1) & 1);
            issueA(g + 1, true,  (g + 1) & 1);
        }
        if (t + 1 < NSTG_) issueB(t + 1);
        cpa_commit();

        const uint32_t Ahi = sb + (uint32_t)(g & 1)*ASZ_;
        const uint32_t Alo = sb + (uint32_t)(2 + (g & 1))*ASZ_;
        const uint32_t Bs  = sb + 4*ASZ_ + (uint32_t)(t & 1)*BSZ_;
        const int kx = s;

#pragma unroll
        for (int kt = 0; kt < 4; kt++) {
            const int c = kt*2 + (gq >> 1);
            uint32_t ah[2][4], al[2][4];
#pragma unroll
            for (int mt = 0; mt < 2; mt++) {
                int sr = m0 + mt*16 + ((gq & 1) << 3) + rq + kx;
                uint32_t off = (uint32_t)sr*128 + (uint32_t)((c ^ (sr & 7)) << 4);
                ldm_x4(ah[mt], Ahi + off);
                ldm_x4(al[mt], Alo + off);
            }
#pragma unroll
            for (int nt = 0; nt < 4; nt++) {
                uint32_t bq[4];
                int brow = n0 + nt*16 + ((gq & 1) << 3) + rq;
                ldm_x4(bq, Bs + (uint32_t)brow*128 + (uint32_t)((c ^ (brow & 7)) << 4));
#pragma unroll
                for (int mt = 0; mt < 2; mt++) {
                    mma_f16(acc[mt][nt*2],     ah[mt], bq[0], bq[2]);
                    mma_f16(acc[mt][nt*2 + 1], ah[mt], bq[1], bq[3]);
                    mma_f16(acc[mt][nt*2],     al[mt], bq[0], bq[2]);
                    mma_f16(acc[mt][nt*2 + 1], al[mt], bq[1], bq[3]);
                }
            }
        }
    }

    // epilogue: bias + relu -> NCHW g_feat
    const int qr = lane >> 2, qc = (lane & 3) * 2;
#pragma unroll
    for (int mt = 0; mt < 2; mt++) {
        int lm = m0 + mt*16 + qr;
#pragma unroll
        for (int nt = 0; nt < 8; nt++) {
            int oc = n0 + nt*8 + qc;
            float b0v = __ldg(bias + oc), b1v = __ldg(bias + oc + 1);
            float* p = g_feat + ((size_t)b*HID_ + oc)*HW_ + y*W_ + x0;
            if (lm < 120) {
                p[lm]       = fmaxf(acc[mt][nt][0] + b0v, 0.f);
                p[lm + HW_] = fmaxf(acc[mt][nt][1] + b1v, 0.f);
            }
            if (lm + 8 < 120) {
                p[lm + 8]       = fmaxf(acc[mt][nt][2] + b0v, 0.f);
                p[lm + 8 + HW_] = fmaxf(acc[mt][nt][3] + b1v, 0.f);
            }
        }
    }
}

// ---------------- 6. fused triple deformable sampling + average ----------------
__device__ __forceinline__ float bilin(const float* __restrict__ f, float ix, float iy) {
    float fx = floorf(ix), fy = floorf(iy);
    float wx = ix - fx, wy = iy - fy;
    int xl = (int)fx, yl = (int)fy;
    int x0i = min(max(xl,     0), W_-1);
    int x1i = min(max(xl + 1, 0), W_-1);
    int y0i = min(max(yl,     0), H_-1);
    int y1i = min(max(yl + 1, 0), H_-1);
    float v00 = f[y0i*W_ + x0i], v01 = f[y0i*W_ + x1i];
    float v10 = f[y1i*W_ + x0i], v11 = f[y1i*W_ + x1i];
    return (v00*(1.f-wx) + v01*wx)*(1.f-wy) + (v10*(1.f-wx) + v11*wx)*wy;
}

__global__ void sample_kernel(float* __restrict__ out) {
    int i = blockIdx.x * 256 + threadIdx.x;
    if (i >= B_*C_*HW_) return;
    int xx = i % W_;
    int y  = (i / W_) % H_;
    int c  = (i / HW_) % C_;
    int b  = i / (C_*HW_);
    const float* offp = g_off + (size_t)b*OCOFF_*HW_ + y*W_ + xx;
    float ox0 = offp[(size_t)( 0 + (c>>3))*HW_], oy0 = offp[(size_t)(16 + (c>>3))*HW_];
    float ox1 = offp[(size_t)(32 + (c>>4))*HW_], oy1 = offp[(size_t)(40 + (c>>4))*HW_];
    float ox2 = offp[(size_t)(48 + (c>>5))*HW_], oy2 = offp[(size_t)(52 + (c>>5))*HW_];
    const float* f = g_feat + (size_t)(b*HID_ + c)*HW_;
    float s = bilin(f, xx + ox0, y + oy0)
            + bilin(f, xx + ox1, y + oy1)
            + bilin(f, xx + ox2, y + oy2);
    out[i] = s * (1.f/3.f);
}

// ---------------- launch ----------------
extern "C" void kernel_launch(void* const* d_in, const int* in_sizes, int n_in,
                              void* d_out, int out_size) {
    const float* x        = (const float*)d_in[0];
    const float* conv_w   = (const float*)d_in[1];
    const float* conv_b   = (const float*)d_in[2];
    const float* gn_gamma = (const float*)d_in[3];
    const float* gn_beta  = (const float*)d_in[4];
    const float* off_w    = (const float*)d_in[5];
    const float* off_b    = (const float*)d_in[6];
    const float* off1_w   = (const float*)d_in[7];
    const float* off1_b   = (const float*)d_in[8];
    const float* off2_w   = (const float*)d_in[9];
    const float* off2_b   = (const float*)d_in[10];
    float* out = (float*)d_out;

    static bool attr_done = false;
    if (!attr_done) {
        cudaFuncSetAttribute(conv1_mma_kernel, cudaFuncAttributeMaxDynamicSharedMemorySize, SMEM_CONV_);
        attr_done = true;
    }

    const int total = B_*C_*HW_;

    // pack path + conv1 FIRST (conv1 = launch #6 so ncu -s 5 -c 1 profiles it)
    zfill_padk_kernel<<<(B_*HP_*WP_*16 + 255)/256, 256>>>();
    zfill_border_kernel<<<(B_*2184*120*2 + 255)/256, 256>>>();
    pack_x_kernel<<<dim3(HW_/32, 28, B_), 256>>>(x);
    pack_coord_kernel<<<(B_*HW_ + 255)/256, 256>>>();
    pack_w_kernel<<<(9*128*KP_ + 255)/256, 256>>>(conv_w);
    conv1_mma_kernel<<<dim3(3, 120, B_), 256, SMEM_CONV_>>>(conv_b);

    mean_kernel<<<(total + 255)/256, 256>>>(x);
    gn_stats_kernel<<<32, 256>>>();
    gn_apply_kernel<<<(total + 255)/256, 256>>>(gn_gamma, gn_beta);
    norm_kernel<<<(B_*HW_ + 7)/8, 256>>>();
    sim_kernel<<<(B_*HW_ + 7)/8, 256>>>();
    offconv_kernel<<<dim3(15, 30, B_), 128>>>(off_w, off_b, off1_w, off1_b, off2_w, off2_b);
    sample_kernel<<<(total + 255)/256, 256>>>(out);
}

// round 10
// speedup vs baseline: 3.0700x; 1.2341x over previous
#include <cuda_runtime.h>
#include <cuda_bf16.h>
#include <cuda_fp16.h>
#include <cstdint>

#define B_ 2
#define N_ 7
#define C_ 128
#define H_ 120
#define W_ 360
#define HW_ (H_*W_)
#define HID_ 128
#define NSIM_ 48
#define OCOFF_ 56
#define ICOFF_ 176

// conv1 mma geometry (single fp16 A, single fp16 B)
#define KP_ 960                    // padded K (898 -> 960, 15 chunks of 64)
#define HP_ 122
#define WP_ 372
#define ASZ_ 16640                 // A tile: 130 rows x 128B
#define BSZ_ 16384                 // B tile: 128 rows x 128B
#define NGRP_ 45                   // 15 kc x 3 ky
#define NSTG_ 135                  // 45 groups x 3 kx stages
#define SMEM_CONV_ (2*ASZ_ + 2*BSZ_)   // A x2 + B x2 = 66048B

// ---------------- scratch (device globals; no runtime alloc) ----------------
__device__ float g_mean[B_*C_*HW_];
__device__ float g_lr  [B_*C_*HW_];
__device__ float g_lrt [(size_t)B_*HW_*C_];
__device__ float g_norm[B_*HW_];
__device__ float g_sim [B_*NSIM_*HW_];
__device__ float g_feat[B_*HID_*HW_];
__device__ float g_off [B_*OCOFF_*HW_];
__device__ float2 g_stats[32];
// padded NHWC fp16 input and per-tap fp16 weights
__device__ __align__(128) __half g_xt[(size_t)B_*HP_*WP_*KP_];
__device__ __align__(128) __half g_wt[9*128*KP_];

// ---------------- f32x2 helpers ----------------
__device__ __forceinline__ unsigned long long dup2(float v) {
    unsigned long long r;
    unsigned u = __float_as_uint(v);
    asm("mov.b64 %0, {%1, %1};" : "=l"(r) : "r"(u));
    return r;
}
__device__ __forceinline__ void fma2(unsigned long long& d, unsigned long long a, unsigned long long b) {
    asm("fma.rn.f32x2 %0, %1, %2, %0;" : "+l"(d) : "l"(a), "l"(b));
}
__device__ __forceinline__ float2 unpack2(unsigned long long v) {
    unsigned lo, hi;
    asm("mov.b64 {%0, %1}, %2;" : "=r"(lo), "=r"(hi) : "l"(v));
    return make_float2(__uint_as_float(lo), __uint_as_float(hi));
}

// ---------------- ptx helpers (cp.async / ldmatrix / mma.sync) ----------------
__device__ __forceinline__ uint32_t smem_u32(const void* p) {
    uint32_t a;
    asm("{ .reg .u64 t; cvta.to.shared.u64 t, %1; cvt.u32.u64 %0, t; }" : "=r"(a) : "l"(p));
    return a;
}
__device__ __forceinline__ void cp_async16(uint32_t dst, const void* src) {
    asm volatile("cp.async.cg.shared.global [%0], [%1], 16;" :: "r"(dst), "l"(src) : "memory");
}
__device__ __forceinline__ void cpa_commit() {
    asm volatile("cp.async.commit_group;" ::: "memory");
}
template<int N> __device__ __forceinline__ void cpa_wait() {
    asm volatile("cp.async.wait_group %0;" :: "n"(N) : "memory");
}
__device__ __forceinline__ void ldm_x4(uint32_t* r, uint32_t addr) {
    asm volatile("ldmatrix.sync.aligned.m8n8.x4.shared.b16 {%0,%1,%2,%3}, [%4];"
        : "=r"(r[0]), "=r"(r[1]), "=r"(r[2]), "=r"(r[3]) : "r"(addr));
}
__device__ __forceinline__ void mma_f16(float* d, const uint32_t* a, uint32_t b0, uint32_t b1) {
    asm volatile("mma.sync.aligned.m16n8k16.row.col.f32.f16.f16.f32 "
        "{%0,%1,%2,%3}, {%4,%5,%6,%7}, {%8,%9}, {%0,%1,%2,%3};"
        : "+f"(d[0]), "+f"(d[1]), "+f"(d[2]), "+f"(d[3])
        : "r"(a[0]), "r"(a[1]), "r"(a[2]), "r"(a[3]), "r"(b0), "r"(b1));
}

// ---------------- 1. mean over N ----------------
__global__ void mean_kernel(const float* __restrict__ x) {
    int i = blockIdx.x * 256 + threadIdx.x;
    if (i >= B_*C_*HW_) return;
    int b = i / (C_*HW_);
    int r = i - b*(C_*HW_);
    const float* p = x + (size_t)b*N_*C_*HW_ + r;
    float s = 0.f;
#pragma unroll
    for (int n = 0; n < N_; n++) s += p[(size_t)n*C_*HW_];
    g_mean[i] = s * (1.f/N_);
}

// ---------------- 2a. GroupNorm stats ----------------
__global__ void gn_stats_kernel() {
    __shared__ double sd[256], sd2[256];
    int bg = blockIdx.x;
    const float* p = g_mean + (size_t)bg * (8*HW_);
    double s = 0.0, ss = 0.0;
    const int n4 = (8*HW_)/4;
    for (int i = threadIdx.x; i < n4; i += 256) {
        float4 v = *(const float4*)(p + (size_t)i*4);
        s  += (double)v.x + v.y + v.z + v.w;
        ss += (double)v.x*v.x + (double)v.y*v.y + (double)v.z*v.z + (double)v.w*v.w;
    }
    sd[threadIdx.x] = s; sd2[threadIdx.x] = ss;
    __syncthreads();
    for (int o = 128; o; o >>= 1) {
        if (threadIdx.x < o) { sd[threadIdx.x] += sd[threadIdx.x+o]; sd2[threadIdx.x] += sd2[threadIdx.x+o]; }
        __syncthreads();
    }
    if (threadIdx.x == 0) {
        double n = 8.0*HW_;
        double mu = sd[0]/n;
        double var = sd2[0]/n - mu*mu;
        g_stats[bg] = make_float2((float)mu, rsqrtf((float)var + 1e-5f));
    }
}

// ---------------- 2b. GroupNorm apply ----------------
__global__ void gn_apply_kernel(const float* __restrict__ gamma, const float* __restrict__ beta) {
    int i = blockIdx.x * 256 + threadIdx.x;
    if (i >= B_*C_*HW_) return;
    int b = i / (C_*HW_);
    int c = (i / HW_) % C_;
    int pix = i % HW_;
    float2 st = g_stats[b*16 + (c >> 3)];
    float v = (g_mean[i] - st.x) * st.y * gamma[c] + beta[c];
    g_lr[i] = v;
    g_lrt[((size_t)(b*HW_ + pix))*C_ + c] = v;
}

// ---------------- 3a. per-pixel L2 norm ----------------
__global__ void norm_kernel() {
    int wid = (blockIdx.x*256 + threadIdx.x) >> 5;
    int lane = threadIdx.x & 31;
    if (wid >= B_*HW_) return;
    float4 v = *(const float4*)&g_lrt[(size_t)wid*C_ + lane*4];
    float s = v.x*v.x + v.y*v.y + v.z*v.z + v.w*v.w;
#pragma unroll
    for (int o = 16; o; o >>= 1) s += __shfl_xor_sync(0xffffffffu, s, o);
    if (lane == 0) g_norm[wid] = fmaxf(sqrtf(s), 1e-8f);
}

// ---------------- 3b. cosine similarity ----------------
__global__ void sim_kernel() {
    int wid = (blockIdx.x*256 + threadIdx.x) >> 5;
    int lane = threadIdx.x & 31;
    if (wid >= B_*HW_) return;
    int b = wid / HW_;
    int pix = wid - b*HW_;
    int y = pix / W_, xx = pix - y*W_;
    float4 cv = *(const float4*)&g_lrt[(size_t)wid*C_ + lane*4];
    float inv_cn = 1.f / g_norm[wid];
    int s = 0;
#pragma unroll
    for (int i = 0; i < 7; i++) {
#pragma unroll
        for (int j = 0; j < 7; j++) {
            if (i == 3 && j == 3) continue;
            int ny = y + 2*i - 6, nx = xx + 2*j - 6;
            float sim = 0.f;
            if ((unsigned)ny < H_ && (unsigned)nx < W_) {
                int npid = b*HW_ + ny*W_ + nx;
                float4 nv = *(const float4*)&g_lrt[(size_t)npid*C_ + lane*4];
                float d = cv.x*nv.x + cv.y*nv.y + cv.z*nv.z + cv.w*nv.w;
#pragma unroll
                for (int o = 16; o; o >>= 1) d += __shfl_xor_sync(0xffffffffu, d, o);
                sim = d * inv_cn / g_norm[npid];
            }
            if (lane == 0) g_sim[((size_t)(b*NSIM_ + s)*H_ + y)*W_ + xx] = sim;
            s++;
        }
    }
}

// ---------------- 4. fused offset convs (oc padded to 64), f32x2 ----------------
__global__ void __launch_bounds__(128) offconv_kernel(
        const float* __restrict__ w0, const float* __restrict__ b0a,
        const float* __restrict__ w1, const float* __restrict__ b1a,
        const float* __restrict__ w2, const float* __restrict__ b2a) {
    __shared__ __align__(16) float s_w[9*64];
    __shared__ float s_in[6*26];
    const int tid = threadIdx.x;
    const int b = blockIdx.z;
    const int x0 = blockIdx.x * 24, y0 = blockIdx.y * 4;
    const int pxg = tid & 15, ocg = tid >> 4;
    const int px = (pxg & 3) * 6, py = pxg >> 2;
    const int oc0 = ocg * 8;
    unsigned long long acc[4][6];
#pragma unroll
    for (int p = 0; p < 4; p++)
#pragma unroll
        for (int j = 0; j < 6; j++) acc[p][j] = 0ull;

    for (int ic = 0; ic < ICOFF_; ic++) {
        __syncthreads();
        if (tid < 64) {
            const float* wp;
            if (tid < 32)      wp = w0 + ((size_t)tid*ICOFF_ + ic)*9;
            else if (tid < 48) wp = w1 + ((size_t)(tid-32)*ICOFF_ + ic)*9;
            else if (tid < 56) wp = w2 + ((size_t)(tid-48)*ICOFF_ + ic)*9;
            else               wp = nullptr;
#pragma unroll
            for (int t = 0; t < 9; t++) s_w[t*64 + tid] = wp ? wp[t] : 0.f;
        } else {
            for (int i = tid - 64; i < 156; i += 64) {
                int r = i / 26, cl = i - r*26;
                int gy = y0 + r - 1, gx = x0 + cl - 1;
                float v = 0.f;
                if ((unsigned)gy < H_ && (unsigned)gx < W_) {
                    if (ic < C_) v = g_lr[((size_t)(b*C_ + ic)*H_ + gy)*W_ + gx];
                    else         v = g_sim[((size_t)(b*NSIM_ + (ic - C_))*H_ + gy)*W_ + gx];
                }
                s_in[r*26 + cl] = v;
            }
        }
        __syncthreads();
#pragma unroll
        for (int ky = 0; ky < 3; ky++) {
            unsigned long long ind[8];
#pragma unroll
            for (int j = 0; j < 8; j++) ind[j] = dup2(s_in[(py+ky)*26 + px + j]);
#pragma unroll
            for (int kx = 0; kx < 3; kx++) {
                const int t = ky*3 + kx;
                unsigned long long wA = *(const unsigned long long*)&s_w[t*64 + oc0];
                unsigned long long wB = *(const unsigned long long*)&s_w[t*64 + oc0 + 2];
                unsigned long long wC = *(const unsigned long long*)&s_w[t*64 + oc0 + 4];
                unsigned long long wD = *(const unsigned long long*)&s_w[t*64 + oc0 + 6];
#pragma unroll
                for (int j = 0; j < 6; j++) {
                    fma2(acc[0][j], wA, ind[kx+j]);
                    fma2(acc[1][j], wB, ind[kx+j]);
                    fma2(acc[2][j], wC, ind[kx+j]);
                    fma2(acc[3][j], wD, ind[kx+j]);
                }
            }
        }
    }
    int oy = y0 + py;
#pragma unroll
    for (int p = 0; p < 4; p++) {
        int oc = oc0 + 2*p;
        if (oc >= OCOFF_) continue;
        float bb0 = (oc   < 32) ? b0a[oc]   : (oc   < 48 ? b1a[oc-32]   : b2a[oc-48]);
        float bb1 = (oc+1 < 32) ? b0a[oc+1] : (oc+1 < 48 ? b1a[oc-31] : b2a[oc-47]);
        float* o0 = g_off + ((size_t)(b*OCOFF_ + oc)*H_ + oy)*W_ + x0 + px;
        float* o1 = o0 + HW_;
#pragma unroll
        for (int j = 0; j < 6; j++) {
            float2 v = unpack2(acc[p][j]);
            o0[j] = v.x + bb0;
            o1[j] = v.y + bb1;
        }
    }
}

// ---------------- 5a. targeted zero-fill (pad-k columns, all pixels) ----------------
__global__ void zfill_padk_kernel() {
    int i = blockIdx.x * 256 + threadIdx.x;
    const int total = B_*HP_*WP_ * 8;   // px * 8 chunks (hi buf only)
    if (i >= total) return;
    int px = i >> 3;
    int ch = i & 7;
    char* base = (char*)g_xt + (size_t)px*(KP_*2) + 1792 + ch*16;
    *(uint4*)base = make_uint4(0u,0u,0u,0u);
}

// ---------------- 5b. targeted zero-fill (border pixels, full K) ----------------
__global__ void zfill_border_kernel() {
    int i = blockIdx.x * 256 + threadIdx.x;
    const int total = B_ * 2184 * 120;
    if (i >= total) return;
    int ch = i % 120;
    int r = i / 120;
    int p = r % 2184;
    int b = r / 2184;
    int y, x;
    if (p < 744) { y = (p < 372) ? 0 : 121; x = p % 372; }
    else {
        int q = p - 744;
        y = 1 + q / 12;
        int m = q % 12;
        x = (m == 0) ? 0 : (360 + m);
    }
    char* base = (char*)g_xt + (((size_t)b*HP_ + y)*WP_ + x)*(KP_*2) + ch*16;
    *(uint4*)base = make_uint4(0u,0u,0u,0u);
}

// ---------------- 5c. pack x (NCHW fp32 -> padded NHWC fp16) ----------------
__global__ void pack_x_kernel(const float* __restrict__ x) {
    __shared__ float t[32][33];
    int b  = blockIdx.z;
    int cg = blockIdx.y;
    int pg = blockIdx.x;
    int tx = threadIdx.x & 31, ty = threadIdx.x >> 5;
    int pix0 = pg * 32;
    const float* src = x + ((size_t)b*896 + cg*32)*HW_ + pix0;
#pragma unroll
    for (int k = 0; k < 4; k++)
        t[ty + 8*k][tx] = src[(size_t)(ty + 8*k)*HW_ + tx];
    __syncthreads();
#pragma unroll
    for (int k = 0; k < 4; k++) {
        int p = pix0 + ty + 8*k;
        int yy = p / W_, xx = p - yy*W_;
        size_t ro = (((size_t)b*HP_ + yy + 1)*WP_ + (xx + 1))*KP_ + cg*32;
        g_xt[ro + tx] = __float2half(t[tx][ty + 8*k]);
    }
}

// ---------------- 5d. coord channels (k=896 gx, k=897 gy) ----------------
__global__ void pack_coord_kernel() {
    int i = blockIdx.x * 256 + threadIdx.x;
    if (i >= B_*HW_) return;
    int b = i / HW_, p = i - b*HW_;
    int yy = p / W_, xx = p - yy*W_;
    size_t ro = (((size_t)b*HP_ + yy + 1)*WP_ + (xx + 1))*KP_;
    g_xt[ro + 896] = __float2half(xx*(2.f/(W_-1)) - 1.f);
    g_xt[ro + 897] = __float2half(yy*(2.f/(H_-1)) - 1.f);
}

// ---------------- 5e. pack weights (per tap, K-major, fp16) ----------------
__global__ void pack_w_kernel(const float* __restrict__ w) {
    int i = blockIdx.x * 256 + threadIdx.x;
    if (i >= 9*128*KP_) return;
    int tap = i / (128*KP_);
    int r = i - tap*(128*KP_);
    int oc = r / KP_, k = r - oc*KP_;
    float v = (k < 898) ? w[((size_t)oc*898 + k)*9 + tap] : 0.f;
    g_wt[i] = __float2half(v);
}

// ---------------- 5f. conv1: mma.sync fp16, A-reuse across kx ----------------
// per CTA (256 thr): M=128 px (one y row, x-tile of 120+halo), N=128 oc.
// groups g=(kc,ky): load A once (130 rows); 3 B-stages (kx=0,1,2),
// each stage computes acc += A*B (64 HMMA/warp).
extern __shared__ char conv_smem[];

__global__ void __launch_bounds__(256, 2) conv1_mma_kernel(const float* __restrict__ bias) {
    const uint32_t sb = smem_u32(conv_smem);
    const int tid = threadIdx.x;
    const int b = blockIdx.z, y = blockIdx.y, x0 = blockIdx.x * 120;
    const int warp = tid >> 5, lane = tid & 31;
    const int m0 = (warp >> 1) * 32, n0 = (warp & 1) * 64;   // 4x2 warp grid

    float acc[2][8][4];
#pragma unroll
    for (int mt = 0; mt < 2; mt++)
#pragma unroll
        for (int nt = 0; nt < 8; nt++)
#pragma unroll
            for (int e = 0; e < 4; e++) acc[mt][nt][e] = 0.f;

    const int lrow = tid >> 1, cb = (tid & 1) * 4;

    // buffers: A[i]=sb+i*ASZ, B[i]=sb+2*ASZ+i*BSZ
    auto issueA = [&](int g, int bufi) {
        int ky = g % 3, kc = g / 3;
        const char* src0 = (const char*)(g_xt + (((size_t)b*HP_ + y + ky)*WP_ + x0)*KP_ + kc*64);
        uint32_t dstBase = sb + (uint32_t)bufi*ASZ_;
        {
            const char* s = src0 + (size_t)lrow * (KP_*2);
            uint32_t d = dstBase + (uint32_t)lrow * 128;
#pragma unroll
            for (int t = 0; t < 4; t++) {
                int c = cb + t;
                cp_async16(d + (uint32_t)((c ^ (lrow & 7)) << 4), s + c*16);
            }
        }
        if (tid < 4) {
            int r2 = 128 + (tid >> 1);
            int cb2 = (tid & 1) * 4;
            const char* s = src0 + (size_t)r2 * (KP_*2);
            uint32_t d = dstBase + (uint32_t)r2 * 128;
#pragma unroll
            for (int t = 0; t < 4; t++) {
                int c = cb2 + t;
                cp_async16(d + (uint32_t)((c ^ (r2 & 7)) << 4), s + c*16);
            }
        }
    };

    auto issueB = [&](int t) {
        int g = t / 3, s = t - g*3;     // s = kx
        int ky = g % 3, kc = g / 3;
        const char* src = (const char*)(g_wt + ((size_t)(ky*3 + s)*128 + lrow)*KP_ + kc*64);
        uint32_t d = sb + 2*ASZ_ + (uint32_t)(t & 1)*BSZ_ + (uint32_t)lrow * 128;
#pragma unroll
        for (int tt = 0; tt < 4; tt++) {
            int c = cb + tt;
            cp_async16(d + (uint32_t)((c ^ (lrow & 7)) << 4), src + c*16);
        }
    };

    // prologue: stage 0's A and B
    issueA(0, 0);
    issueB(0);
    cpa_commit();

    const int gq = lane >> 3, rq = lane & 7;
    for (int t = 0; t < NSTG_; t++) {
        const int g = t / 3, s = t - g*3;
        cpa_wait<0>();
        __syncthreads();
        // issue next stage (writes opposite-parity buffers; this stage's reads are
        // protected because all warps passed the barrier after finishing stage t-1)
        if (s == 0 && g + 1 < NGRP_) issueA(g + 1, (g + 1) & 1);
        if (t + 1 < NSTG_) issueB(t + 1);
        cpa_commit();

        const uint32_t As = sb + (uint32_t)(g & 1)*ASZ_;
        const uint32_t Bs = sb + 2*ASZ_ + (uint32_t)(t & 1)*BSZ_;
        const int kx = s;

#pragma unroll
        for (int kt = 0; kt < 4; kt++) {
            const int c = kt*2 + (gq >> 1);
            uint32_t a[2][4];
#pragma unroll
            for (int mt = 0; mt < 2; mt++) {
                int sr = m0 + mt*16 + ((gq & 1) << 3) + rq + kx;
                uint32_t off = (uint32_t)sr*128 + (uint32_t)((c ^ (sr & 7)) << 4);
                ldm_x4(a[mt], As + off);
            }
#pragma unroll
            for (int nt = 0; nt < 4; nt++) {
                uint32_t bq[4];
                int brow = n0 + nt*16 + ((gq & 1) << 3) + rq;
                ldm_x4(bq, Bs + (uint32_t)brow*128 + (uint32_t)((c ^ (brow & 7)) << 4));
#pragma unroll
                for (int mt = 0; mt < 2; mt++) {
                    mma_f16(acc[mt][nt*2],     a[mt], bq[0], bq[2]);
                    mma_f16(acc[mt][nt*2 + 1], a[mt], bq[1], bq[3]);
                }
            }
        }
    }

    // epilogue: bias + relu -> NCHW g_feat
    const int qr = lane >> 2, qc = (lane & 3) * 2;
#pragma unroll
    for (int mt = 0; mt < 2; mt++) {
        int lm = m0 + mt*16 + qr;
#pragma unroll
        for (int nt = 0; nt < 8; nt++) {
            int oc = n0 + nt*8 + qc;
            float b0v = __ldg(bias + oc), b1v = __ldg(bias + oc + 1);
            float* p = g_feat + ((size_t)b*HID_ + oc)*HW_ + y*W_ + x0;
            if (lm < 120) {
                p[lm]       = fmaxf(acc[mt][nt][0] + b0v, 0.f);
                p[lm + HW_] = fmaxf(acc[mt][nt][1] + b1v, 0.f);
            }
            if (lm + 8 < 120) {
                p[lm + 8]       = fmaxf(acc[mt][nt][2] + b0v, 0.f);
                p[lm + 8 + HW_] = fmaxf(acc[mt][nt][3] + b1v, 0.f);
            }
        }
    }
}

// ---------------- 6. fused triple deformable sampling + average ----------------
__device__ __forceinline__ float bilin(const float* __restrict__ f, float ix, float iy) {
    float fx = floorf(ix), fy = floorf(iy);
    float wx = ix - fx, wy = iy - fy;
    int xl = (int)fx, yl = (int)fy;
    int x0i = min(max(xl,     0), W_-1);
    int x1i = min(max(xl + 1, 0), W_-1);
    int y0i = min(max(yl,     0), H_-1);
    int y1i = min(max(yl + 1, 0), H_-1);
    float v00 = f[y0i*W_ + x0i], v01 = f[y0i*W_ + x1i];
    float v10 = f[y1i*W_ + x0i], v11 = f[y1i*W_ + x1i];
    return (v00*(1.f-wx) + v01*wx)*(1.f-wy) + (v10*(1.f-wx) + v11*wx)*wy;
}

__global__ void sample_kernel(float* __restrict__ out) {
    int i = blockIdx.x * 256 + threadIdx.x;
    if (i >= B_*C_*HW_) return;
    int xx = i % W_;
    int y  = (i / W_) % H_;
    int c  = (i / HW_) % C_;
    int b  = i / (C_*HW_);
    const float* offp = g_off + (size_t)b*OCOFF_*HW_ + y*W_ + xx;
    float ox0 = offp[(size_t)( 0 + (c>>3))*HW_], oy0 = offp[(size_t)(16 + (c>>3))*HW_];
    float ox1 = offp[(size_t)(32 + (c>>4))*HW_], oy1 = offp[(size_t)(40 + (c>>4))*HW_];
    float ox2 = offp[(size_t)(48 + (c>>5))*HW_], oy2 = offp[(size_t)(52 + (c>>5))*HW_];
    const float* f = g_feat + (size_t)(b*HID_ + c)*HW_;
    float s = bilin(f, xx + ox0, y + oy0)
            + bilin(f, xx + ox1, y + oy1)
            + bilin(f, xx + ox2, y + oy2);
    out[i] = s * (1.f/3.f);
}

// ---------------- launch ----------------
extern "C" void kernel_launch(void* const* d_in, const int* in_sizes, int n_in,
                              void* d_out, int out_size) {
    const float* x        = (const float*)d_in[0];
    const float* conv_w   = (const float*)d_in[1];
    const float* conv_b   = (const float*)d_in[2];
    const float* gn_gamma = (const float*)d_in[3];
    const float* gn_beta  = (const float*)d_in[4];
    const float* off_w    = (const float*)d_in[5];
    const float* off_b    = (const float*)d_in[6];
    const float* off1_w   = (const float*)d_in[7];
    const float* off1_b   = (const float*)d_in[8];
    const float* off2_w   = (const float*)d_in[9];
    const float* off2_b   = (const float*)d_in[10];
    float* out = (float*)d_out;

    static bool attr_done = false;
    if (!attr_done) {
        cudaFuncSetAttribute(conv1_mma_kernel, cudaFuncAttributeMaxDynamicSharedMemorySize, SMEM_CONV_);
        attr_done = true;
    }

    const int total = B_*C_*HW_;

    // pack path + conv1 first
    zfill_padk_kernel<<<(B_*HP_*WP_*8 + 255)/256, 256>>>();
    zfill_border_kernel<<<(B_*2184*120 + 255)/256, 256>>>();
    pack_x_kernel<<<dim3(HW_/32, 28, B_), 256>>>(x);
    pack_coord_kernel<<<(B_*HW_ + 255)/256, 256>>>();
    pack_w_kernel<<<(9*128*KP_ + 255)/256, 256>>>(conv_w);
    conv1_mma_kernel<<<dim3(3, 120, B_), 256, SMEM_CONV_>>>(conv_b);

    mean_kernel<<<(total + 255)/256, 256>>>(x);
    gn_stats_kernel<<<32, 256>>>();
    gn_apply_kernel<<<(total + 255)/256, 256>>>(gn_gamma, gn_beta);
    norm_kernel<<<(B_*HW_ + 7)/8, 256>>>();
    sim_kernel<<<(B_*HW_ + 7)/8, 256>>>();
    offconv_kernel<<<dim3(15, 30, B_), 128>>>(off_w, off_b, off1_w, off1_b, off2_w, off2_b);
    sample_kernel<<<(total + 255)/256, 256>>>(out);
}

// round 11
// speedup vs baseline: 4.2566x; 1.3865x over previous
#include <cuda_runtime.h>
#include <cuda_bf16.h>
#include <cuda_fp16.h>
#include <cstdint>

#define B_ 2
#define N_ 7
#define C_ 128
#define H_ 120
#define W_ 360
#define HW_ (H_*W_)
#define HID_ 128
#define OCOFF_ 56

// conv1 mma geometry (single fp16 A, single fp16 B)
#define KP_ 960                    // padded K (898 -> 960, 15 chunks of 64)
#define HP_ 122
#define WP_ 372
#define ASZ_ 16640                 // A tile: 130 rows x 128B
#define BSZ_ 16384                 // B tile: 128 rows x 128B
#define NGRP_ 45                   // 15 kc x 3 ky
#define NSTG_ 135                  // 45 groups x 3 kx stages
#define SMEM_CONV_ (2*ASZ_ + 2*BSZ_)   // 66048B

// offconv mma geometry (K = 128 lr + 48 sim + 16 pad = 192; N = 56 -> 64)
#define KO_ 192
#define OBSZ_ 8192                 // B tile: 64 rows x 128B
#define ONSTG_ 27                  // 9 groups (3 kc x 3 ky) x 3 kx
#define SMEM_OFF_ (2*ASZ_ + 2*OBSZ_)   // 49664B

// ---------------- scratch (device globals; no runtime alloc) ----------------
__device__ float g_mean[B_*C_*HW_];
__device__ float g_lrt [(size_t)B_*HW_*C_];   // group-normed, NHWC fp32
__device__ float g_norm[B_*HW_];
__device__ float g_feat[B_*HID_*HW_];
__device__ float g_off [B_*OCOFF_*HW_];
__device__ float2 g_stats[32];
// padded NHWC fp16 input / weights for conv1
__device__ __align__(128) __half g_xt[(size_t)B_*HP_*WP_*KP_];
__device__ __align__(128) __half g_wt[9*128*KP_];
// padded NHWC fp16 lr+sim (192 ch) / packed offset weights
__device__ __align__(128) __half g_ls[(size_t)B_*HP_*WP_*KO_];
__device__ __align__(128) __half g_wo[9*64*KO_];

// ---------------- ptx helpers (cp.async / ldmatrix / mma.sync) ----------------
__device__ __forceinline__ uint32_t smem_u32(const void* p) {
    uint32_t a;
    asm("{ .reg .u64 t; cvta.to.shared.u64 t, %1; cvt.u32.u64 %0, t; }" : "=r"(a) : "l"(p));
    return a;
}
__device__ __forceinline__ void cp_async16(uint32_t dst, const void* src) {
    asm volatile("cp.async.cg.shared.global [%0], [%1], 16;" :: "r"(dst), "l"(src) : "memory");
}
__device__ __forceinline__ void cpa_commit() {
    asm volatile("cp.async.commit_group;" ::: "memory");
}
template<int N> __device__ __forceinline__ void cpa_wait() {
    asm volatile("cp.async.wait_group %0;" :: "n"(N) : "memory");
}
__device__ __forceinline__ void ldm_x4(uint32_t* r, uint32_t addr) {
    asm volatile("ldmatrix.sync.aligned.m8n8.x4.shared.b16 {%0,%1,%2,%3}, [%4];"
        : "=r"(r[0]), "=r"(r[1]), "=r"(r[2]), "=r"(r[3]) : "r"(addr));
}
__device__ __forceinline__ void mma_f16(float* d, const uint32_t* a, uint32_t b0, uint32_t b1) {
    asm volatile("mma.sync.aligned.m16n8k16.row.col.f32.f16.f16.f32 "
        "{%0,%1,%2,%3}, {%4,%5,%6,%7}, {%8,%9}, {%0,%1,%2,%3};"
        : "+f"(d[0]), "+f"(d[1]), "+f"(d[2]), "+f"(d[3])
        : "r"(a[0]), "r"(a[1]), "r"(a[2]), "r"(a[3]), "r"(b0), "r"(b1));
}

// ---------------- 1. mean over N ----------------
__global__ void mean_kernel(const float* __restrict__ x) {
    int i = blockIdx.x * 256 + threadIdx.x;
    if (i >= B_*C_*HW_) return;
    int b = i / (C_*HW_);
    int r = i - b*(C_*HW_);
    const float* p = x + (size_t)b*N_*C_*HW_ + r;
    float s = 0.f;
#pragma unroll
    for (int n = 0; n < N_; n++) s += p[(size_t)n*C_*HW_];
    g_mean[i] = s * (1.f/N_);
}

// ---------------- 2a. GroupNorm stats ----------------
__global__ void gn_stats_kernel() {
    __shared__ double sd[256], sd2[256];
    int bg = blockIdx.x;
    const float* p = g_mean + (size_t)bg * (8*HW_);
    double s = 0.0, ss = 0.0;
    const int n4 = (8*HW_)/4;
    for (int i = threadIdx.x; i < n4; i += 256) {
        float4 v = *(const float4*)(p + (size_t)i*4);
        s  += (double)v.x + v.y + v.z + v.w;
        ss += (double)v.x*v.x + (double)v.y*v.y + (double)v.z*v.z + (double)v.w*v.w;
    }
    sd[threadIdx.x] = s; sd2[threadIdx.x] = ss;
    __syncthreads();
    for (int o = 128; o; o >>= 1) {
        if (threadIdx.x < o) { sd[threadIdx.x] += sd[threadIdx.x+o]; sd2[threadIdx.x] += sd2[threadIdx.x+o]; }
        __syncthreads();
    }
    if (threadIdx.x == 0) {
        double n = 8.0*HW_;
        double mu = sd[0]/n;
        double var = sd2[0]/n - mu*mu;
        g_stats[bg] = make_float2((float)mu, rsqrtf((float)var + 1e-5f));
    }
}

// ---------------- 2b. GroupNorm apply -> g_lrt (fp32 NHWC) + g_ls ch 0..127 ----------------
__global__ void gn_apply_kernel(const float* __restrict__ gamma, const float* __restrict__ beta) {
    int i = blockIdx.x * 256 + threadIdx.x;
    if (i >= B_*C_*HW_) return;
    int b = i / (C_*HW_);
    int c = (i / HW_) % C_;
    int pix = i % HW_;
    float2 st = g_stats[b*16 + (c >> 3)];
    float v = (g_mean[i] - st.x) * st.y * gamma[c] + beta[c];
    g_lrt[((size_t)(b*HW_ + pix))*C_ + c] = v;
    int yy = pix / W_, xx = pix - yy*W_;
    g_ls[(((size_t)b*HP_ + yy + 1)*WP_ + (xx + 1))*KO_ + c] = __float2half(v);
}

// ---------------- 3a. per-pixel L2 norm ----------------
__global__ void norm_kernel() {
    int wid = (blockIdx.x*256 + threadIdx.x) >> 5;
    int lane = threadIdx.x & 31;
    if (wid >= B_*HW_) return;
    float4 v = *(const float4*)&g_lrt[(size_t)wid*C_ + lane*4];
    float s = v.x*v.x + v.y*v.y + v.z*v.z + v.w*v.w;
#pragma unroll
    for (int o = 16; o; o >>= 1) s += __shfl_xor_sync(0xffffffffu, s, o);
    if (lane == 0) g_norm[wid] = fmaxf(sqrtf(s), 1e-8f);
}

// ---------------- 3b. cosine similarity (symmetric halving) ----------------
// sims[t] at p with offset d equals sims[47-t] at p+d. Compute t=0..23, write both.
// Out-of-range entries stay zero (g_ls pre-zeroed).
__global__ void sim_kernel() {
    int wid = (blockIdx.x*256 + threadIdx.x) >> 5;
    int lane = threadIdx.x & 31;
    if (wid >= B_*HW_) return;
    int b = wid / HW_;
    int pix = wid - b*HW_;
    int y = pix / W_, xx = pix - y*W_;
    float4 cv = *(const float4*)&g_lrt[(size_t)wid*C_ + lane*4];
    float inv_cn = 1.f / g_norm[wid];
    size_t po = (((size_t)b*HP_ + y + 1)*WP_ + (xx + 1))*KO_ + 128;
#pragma unroll
    for (int t = 0; t < 24; t++) {
        const int i = t / 7, j = t - 7*(t/7);
        int ny = y + 2*i - 6, nx = xx + 2*j - 6;
        if ((unsigned)ny < H_ && (unsigned)nx < W_) {
            int npid = b*HW_ + ny*W_ + nx;
            float4 nv = *(const float4*)&g_lrt[(size_t)npid*C_ + lane*4];
            float d = cv.x*nv.x + cv.y*nv.y + cv.z*nv.z + cv.w*nv.w;
#pragma unroll
            for (int o = 16; o; o >>= 1) d += __shfl_xor_sync(0xffffffffu, d, o);
            if (lane == 0) {
                float v = d * inv_cn / g_norm[npid];
                __half hv = __float2half(v);
                g_ls[po + t] = hv;
                size_t qo = (((size_t)b*HP_ + ny + 1)*WP_ + (nx + 1))*KO_ + 128;
                g_ls[qo + 47 - t] = hv;
            }
        }
    }
}

// ---------------- zfill: whole g_ls buffer ----------------
__global__ void zfill_ls_kernel() {
    size_t n4 = ((size_t)B_*HP_*WP_*KO_*2) / 16;
    size_t i = (size_t)blockIdx.x * 256 + threadIdx.x;
    if (i < n4) ((uint4*)g_ls)[i] = make_uint4(0u,0u,0u,0u);
}

// ---------------- pack offset weights: [9 tap][64 oc][192 k] fp16 ----------------
__global__ void pack_wo_kernel(const float* __restrict__ w0, const float* __restrict__ w1,
                               const float* __restrict__ w2) {
    int i = blockIdx.x * 256 + threadIdx.x;
    if (i >= 9*64*KO_) return;
    int tap = i / (64*KO_);
    int r = i - tap*(64*KO_);
    int oc = r / KO_, k = r - oc*KO_;
    float v = 0.f;
    if (k < 176) {
        if (oc < 32)      v = w0[((size_t)oc*176 + k)*9 + tap];
        else if (oc < 48) v = w1[((size_t)(oc-32)*176 + k)*9 + tap];
        else if (oc < 56) v = w2[((size_t)(oc-48)*176 + k)*9 + tap];
    }
    g_wo[i] = __float2half(v);
}

// ---------------- conv1 pack path ----------------
__global__ void zfill_padk_kernel() {
    int i = blockIdx.x * 256 + threadIdx.x;
    const int total = B_*HP_*WP_ * 8;
    if (i >= total) return;
    int px = i >> 3;
    int ch = i & 7;
    char* base = (char*)g_xt + (size_t)px*(KP_*2) + 1792 + ch*16;
    *(uint4*)base = make_uint4(0u,0u,0u,0u);
}

__global__ void zfill_border_kernel() {
    int i = blockIdx.x * 256 + threadIdx.x;
    const int total = B_ * 2184 * 120;
    if (i >= total) return;
    int ch = i % 120;
    int r = i / 120;
    int p = r % 2184;
    int b = r / 2184;
    int y, x;
    if (p < 744) { y = (p < 372) ? 0 : 121; x = p % 372; }
    else {
        int q = p - 744;
        y = 1 + q / 12;
        int m = q % 12;
        x = (m == 0) ? 0 : (360 + m);
    }
    char* base = (char*)g_xt + (((size_t)b*HP_ + y)*WP_ + x)*(KP_*2) + ch*16;
    *(uint4*)base = make_uint4(0u,0u,0u,0u);
}

__global__ void pack_x_kernel(const float* __restrict__ x) {
    __shared__ float t[32][33];
    int b  = blockIdx.z;
    int cg = blockIdx.y;
    int pg = blockIdx.x;
    int tx = threadIdx.x & 31, ty = threadIdx.x >> 5;
    int pix0 = pg * 32;
    const float* src = x + ((size_t)b*896 + cg*32)*HW_ + pix0;
#pragma unroll
    for (int k = 0; k < 4; k++)
        t[ty + 8*k][tx] = src[(size_t)(ty + 8*k)*HW_ + tx];
    __syncthreads();
#pragma unroll
    for (int k = 0; k < 4; k++) {
        int p = pix0 + ty + 8*k;
        int yy = p / W_, xx = p - yy*W_;
        size_t ro = (((size_t)b*HP_ + yy + 1)*WP_ + (xx + 1))*KP_ + cg*32;
        g_xt[ro + tx] = __float2half(t[tx][ty + 8*k]);
    }
}

__global__ void pack_coord_kernel() {
    int i = blockIdx.x * 256 + threadIdx.x;
    if (i >= B_*HW_) return;
    int b = i / HW_, p = i - b*HW_;
    int yy = p / W_, xx = p - yy*W_;
    size_t ro = (((size_t)b*HP_ + yy + 1)*WP_ + (xx + 1))*KP_;
    g_xt[ro + 896] = __float2half(xx*(2.f/(W_-1)) - 1.f);
    g_xt[ro + 897] = __float2half(yy*(2.f/(H_-1)) - 1.f);
}

__global__ void pack_w_kernel(const float* __restrict__ w) {
    int i = blockIdx.x * 256 + threadIdx.x;
    if (i >= 9*128*KP_) return;
    int tap = i / (128*KP_);
    int r = i - tap*(128*KP_);
    int oc = r / KP_, k = r - oc*KP_;
    float v = (k < 898) ? w[((size_t)oc*898 + k)*9 + tap] : 0.f;
    g_wt[i] = __float2half(v);
}

// ---------------- conv1: mma.sync fp16, A-reuse across kx ----------------
extern __shared__ char conv_smem[];

__global__ void __launch_bounds__(256, 2) conv1_mma_kernel(const float* __restrict__ bias) {
    const uint32_t sb = smem_u32(conv_smem);
    const int tid = threadIdx.x;
    const int b = blockIdx.z, y = blockIdx.y, x0 = blockIdx.x * 120;
    const int warp = tid >> 5, lane = tid & 31;
    const int m0 = (warp >> 1) * 32, n0 = (warp & 1) * 64;

    float acc[2][8][4];
#pragma unroll
    for (int mt = 0; mt < 2; mt++)
#pragma unroll
        for (int nt = 0; nt < 8; nt++)
#pragma unroll
            for (int e = 0; e < 4; e++) acc[mt][nt][e] = 0.f;

    const int lrow = tid >> 1, cb = (tid & 1) * 4;

    auto issueA = [&](int g, int bufi) {
        int ky = g % 3, kc = g / 3;
        const char* src0 = (const char*)(g_xt + (((size_t)b*HP_ + y + ky)*WP_ + x0)*KP_ + kc*64);
        uint32_t dstBase = sb + (uint32_t)bufi*ASZ_;
        {
            const char* s = src0 + (size_t)lrow * (KP_*2);
            uint32_t d = dstBase + (uint32_t)lrow * 128;
#pragma unroll
            for (int t = 0; t < 4; t++) {
                int c = cb + t;
                cp_async16(d + (uint32_t)((c ^ (lrow & 7)) << 4), s + c*16);
            }
        }
        if (tid < 4) {
            int r2 = 128 + (tid >> 1);
            int cb2 = (tid & 1) * 4;
            const char* s = src0 + (size_t)r2 * (KP_*2);
            uint32_t d = dstBase + (uint32_t)r2 * 128;
#pragma unroll
            for (int t = 0; t < 4; t++) {
                int c = cb2 + t;
                cp_async16(d + (uint32_t)((c ^ (r2 & 7)) << 4), s + c*16);
            }
        }
    };

    auto issueB = [&](int t) {
        int g = t / 3, s = t - g*3;
        int ky = g % 3, kc = g / 3;
        const char* src = (const char*)(g_wt + ((size_t)(ky*3 + s)*128 + lrow)*KP_ + kc*64);
        uint32_t d = sb + 2*ASZ_ + (uint32_t)(t & 1)*BSZ_ + (uint32_t)lrow * 128;
#pragma unroll
        for (int tt = 0; tt < 4; tt++) {
            int c = cb + tt;
            cp_async16(d + (uint32_t)((c ^ (lrow & 7)) << 4), src + c*16);
        }
    };

    issueA(0, 0);
    issueB(0);
    cpa_commit();

    const int gq = lane >> 3, rq = lane & 7;
    for (int t = 0; t < NSTG_; t++) {
        const int g = t / 3, s = t - g*3;
        cpa_wait<0>();
        __syncthreads();
        if (s == 0 && g + 1 < NGRP_) issueA(g + 1, (g + 1) & 1);
        if (t + 1 < NSTG_) issueB(t + 1);
        cpa_commit();

        const uint32_t As = sb + (uint32_t)(g & 1)*ASZ_;
        const uint32_t Bs = sb + 2*ASZ_ + (uint32_t)(t & 1)*BSZ_;
        const int kx = s;

#pragma unroll
        for (int kt = 0; kt < 4; kt++) {
            const int c = kt*2 + (gq >> 1);
            uint32_t a[2][4];
#pragma unroll
            for (int mt = 0; mt < 2; mt++) {
                int sr = m0 + mt*16 + ((gq & 1) << 3) + rq + kx;
                uint32_t off = (uint32_t)sr*128 + (uint32_t)((c ^ (sr & 7)) << 4);
                ldm_x4(a[mt], As + off);
            }
#pragma unroll
            for (int nt = 0; nt < 4; nt++) {
                uint32_t bq[4];
                int brow = n0 + nt*16 + ((gq & 1) << 3) + rq;
                ldm_x4(bq, Bs + (uint32_t)brow*128 + (uint32_t)((c ^ (brow & 7)) << 4));
#pragma unroll
                for (int mt = 0; mt < 2; mt++) {
                    mma_f16(acc[mt][nt*2],     a[mt], bq[0], bq[2]);
                    mma_f16(acc[mt][nt*2 + 1], a[mt], bq[1], bq[3]);
                }
            }
        }
    }

    const int qr = lane >> 2, qc = (lane & 3) * 2;
#pragma unroll
    for (int mt = 0; mt < 2; mt++) {
        int lm = m0 + mt*16 + qr;
#pragma unroll
        for (int nt = 0; nt < 8; nt++) {
            int oc = n0 + nt*8 + qc;
            float b0v = __ldg(bias + oc), b1v = __ldg(bias + oc + 1);
            float* p = g_feat + ((size_t)b*HID_ + oc)*HW_ + y*W_ + x0;
            if (lm < 120) {
                p[lm]       = fmaxf(acc[mt][nt][0] + b0v, 0.f);
                p[lm + HW_] = fmaxf(acc[mt][nt][1] + b1v, 0.f);
            }
            if (lm + 8 < 120) {
                p[lm + 8]       = fmaxf(acc[mt][nt][2] + b0v, 0.f);
                p[lm + 8 + HW_] = fmaxf(acc[mt][nt][3] + b1v, 0.f);
            }
        }
    }
}

// ---------------- offconv: mma.sync fp16 (K=192, N=64) ----------------
__global__ void __launch_bounds__(256, 2) offconv_mma_kernel(
        const float* __restrict__ b0a, const float* __restrict__ b1a,
        const float* __restrict__ b2a) {
    const uint32_t sb = smem_u32(conv_smem);
    const int tid = threadIdx.x;
    const int b = blockIdx.z, y = blockIdx.y, x0 = blockIdx.x * 120;
    const int warp = tid >> 5, lane = tid & 31;
    const int m0 = (warp >> 1) * 32, n0 = (warp & 1) * 32;   // 4x2 warp grid, N=64

    float acc[2][4][4];
#pragma unroll
    for (int mt = 0; mt < 2; mt++)
#pragma unroll
        for (int nt = 0; nt < 4; nt++)
#pragma unroll
            for (int e = 0; e < 4; e++) acc[mt][nt][e] = 0.f;

    const int lrow = tid >> 1, cb = (tid & 1) * 4;

    auto issueA = [&](int g, int bufi) {
        int ky = g % 3, kc = g / 3;
        const char* src0 = (const char*)(g_ls + (((size_t)b*HP_ + y + ky)*WP_ + x0)*KO_ + kc*64);
        uint32_t dstBase = sb + (uint32_t)bufi*ASZ_;
        {
            const char* s = src0 + (size_t)lrow * (KO_*2);
            uint32_t d = dstBase + (uint32_t)lrow * 128;
#pragma unroll
            for (int t = 0; t < 4; t++) {
                int c = cb + t;
                cp_async16(d + (uint32_t)((c ^ (lrow & 7)) << 4), s + c*16);
            }
        }
        if (tid < 4) {
            int r2 = 128 + (tid >> 1);
            int cb2 = (tid & 1) * 4;
            const char* s = src0 + (size_t)r2 * (KO_*2);
            uint32_t d = dstBase + (uint32_t)r2 * 128;
#pragma unroll
            for (int t = 0; t < 4; t++) {
                int c = cb2 + t;
                cp_async16(d + (uint32_t)((c ^ (r2 & 7)) << 4), s + c*16);
            }
        }
    };

    // B tile: 64 oc rows x 128B; 256 threads -> 1 row, 2 chunks each
    auto issueB = [&](int t) {
        int g = t / 3, s = t - g*3;
        int ky = g % 3, kc = g / 3;
        int r = tid >> 2, cb2 = (tid & 3) * 2;
        const char* src = (const char*)(g_wo + ((size_t)(ky*3 + s)*64 + r)*KO_ + kc*64);
        uint32_t d = sb + 2*ASZ_ + (uint32_t)(t & 1)*OBSZ_ + (uint32_t)r * 128;
#pragma unroll
        for (int tt = 0; tt < 2; tt++) {
            int c = cb2 + tt;
            cp_async16(d + (uint32_t)((c ^ (r & 7)) << 4), src + c*16);
        }
    };

    issueA(0, 0);
    issueB(0);
    cpa_commit();

    const int gq = lane >> 3, rq = lane & 7;
    for (int t = 0; t < ONSTG_; t++) {
        const int g = t / 3, s = t - g*3;
        cpa_wait<0>();
        __syncthreads();
        if (s == 0 && g + 1 < 9) issueA(g + 1, (g + 1) & 1);
        if (t + 1 < ONSTG_) issueB(t + 1);
        cpa_commit();

        const uint32_t As = sb + (uint32_t)(g & 1)*ASZ_;
        const uint32_t Bs = sb + 2*ASZ_ + (uint32_t)(t & 1)*OBSZ_;
        const int kx = s;

#pragma unroll
        for (int kt = 0; kt < 4; kt++) {
            const int c = kt*2 + (gq >> 1);
            uint32_t a[2][4];
#pragma unroll
            for (int mt = 0; mt < 2; mt++) {
                int sr = m0 + mt*16 + ((gq & 1) << 3) + rq + kx;
                uint32_t off = (uint32_t)sr*128 + (uint32_t)((c ^ (sr & 7)) << 4);
                ldm_x4(a[mt], As + off);
            }
#pragma unroll
            for (int nt = 0; nt < 2; nt++) {
                uint32_t bq[4];
                int brow = n0 + nt*16 + ((gq & 1) << 3) + rq;
                ldm_x4(bq, Bs + (uint32_t)brow*128 + (uint32_t)((c ^ (brow & 7)) << 4));
#pragma unroll
                for (int mt = 0; mt < 2; mt++) {
                    mma_f16(acc[mt][nt*2],     a[mt], bq[0], bq[2]);
                    mma_f16(acc[mt][nt*2 + 1], a[mt], bq[1], bq[3]);
                }
            }
        }
    }

    const int qr = lane >> 2, qc = (lane & 3) * 2;
#pragma unroll
    for (int mt = 0; mt < 2; mt++) {
        int lm = m0 + mt*16 + qr;
#pragma unroll
        for (int nt = 0; nt < 4; nt++) {
            int oc = n0 + nt*8 + qc;   // even, < 64
            if (oc >= OCOFF_) continue;
            float b0v = (oc   < 32) ? b0a[oc]   : (oc   < 48 ? b1a[oc-32] : b2a[oc-48]);
            float b1v = (oc+1 < 32) ? b0a[oc+1] : (oc+1 < 48 ? b1a[oc-31] : b2a[oc-47]);
            float* p = g_off + ((size_t)b*OCOFF_ + oc)*HW_ + y*W_ + x0;
            if (lm < 120) {
                p[lm]       = acc[mt][nt][0] + b0v;
                p[lm + HW_] = acc[mt][nt][1] + b1v;
            }
            if (lm + 8 < 120) {
                p[lm + 8]       = acc[mt][nt][2] + b0v;
                p[lm + 8 + HW_] = acc[mt][nt][3] + b1v;
            }
        }
    }
}

// ---------------- fused triple deformable sampling + average ----------------
__device__ __forceinline__ float bilin(const float* __restrict__ f, float ix, float iy) {
    float fx = floorf(ix), fy = floorf(iy);
    float wx = ix - fx, wy = iy - fy;
    int xl = (int)fx, yl = (int)fy;
    int x0i = min(max(xl,     0), W_-1);
    int x1i = min(max(xl + 1, 0), W_-1);
    int y0i = min(max(yl,     0), H_-1);
    int y1i = min(max(yl + 1, 0), H_-1);
    float v00 = f[y0i*W_ + x0i], v01 = f[y0i*W_ + x1i];
    float v10 = f[y1i*W_ + x0i], v11 = f[y1i*W_ + x1i];
    return (v00*(1.f-wx) + v01*wx)*(1.f-wy) + (v10*(1.f-wx) + v11*wx)*wy;
}

__global__ void sample_kernel(float* __restrict__ out) {
    int i = blockIdx.x * 256 + threadIdx.x;
    if (i >= B_*C_*HW_) return;
    int xx = i % W_;
    int y  = (i / W_) % H_;
    int c  = (i / HW_) % C_;
    int b  = i / (C_*HW_);
    const float* offp = g_off + (size_t)b*OCOFF_*HW_ + y*W_ + xx;
    float ox0 = offp[(size_t)( 0 + (c>>3))*HW_], oy0 = offp[(size_t)(16 + (c>>3))*HW_];
    float ox1 = offp[(size_t)(32 + (c>>4))*HW_], oy1 = offp[(size_t)(40 + (c>>4))*HW_];
    float ox2 = offp[(size_t)(48 + (c>>5))*HW_], oy2 = offp[(size_t)(52 + (c>>5))*HW_];
    const float* f = g_feat + (size_t)(b*HID_ + c)*HW_;
    float s = bilin(f, xx + ox0, y + oy0)
            + bilin(f, xx + ox1, y + oy1)
            + bilin(f, xx + ox2, y + oy2);
    out[i] = s * (1.f/3.f);
}

// ---------------- launch ----------------
extern "C" void kernel_launch(void* const* d_in, const int* in_sizes, int n_in,
                              void* d_out, int out_size) {
    const float* x        = (const float*)d_in[0];
    const float* conv_w   = (const float*)d_in[1];
    const float* conv_b   = (const float*)d_in[2];
    const float* gn_gamma = (const float*)d_in[3];
    const float* gn_beta  = (const float*)d_in[4];
    const float* off_w    = (const float*)d_in[5];
    const float* off_b    = (const float*)d_in[6];
    const float* off1_w   = (const float*)d_in[7];
    const float* off1_b   = (const float*)d_in[8];
    const float* off2_w   = (const float*)d_in[9];
    const float* off2_b   = (const float*)d_in[10];
    float* out = (float*)d_out;

    static bool attr_done = false;
    if (!attr_done) {
        cudaFuncSetAttribute(conv1_mma_kernel, cudaFuncAttributeMaxDynamicSharedMemorySize, SMEM_CONV_);
        cudaFuncSetAttribute(offconv_mma_kernel, cudaFuncAttributeMaxDynamicSharedMemorySize, SMEM_OFF_);
        attr_done = true;
    }

    const int total = B_*C_*HW_;

    // conv1 pack path + conv1
    zfill_padk_kernel<<<(B_*HP_*WP_*8 + 255)/256, 256>>>();
    zfill_border_kernel<<<(B_*2184*120 + 255)/256, 256>>>();
    pack_x_kernel<<<dim3(HW_/32, 28, B_), 256>>>(x);
    pack_coord_kernel<<<(B_*HW_ + 255)/256, 256>>>();
    pack_w_kernel<<<(9*128*KP_ + 255)/256, 256>>>(conv_w);
    conv1_mma_kernel<<<dim3(3, 120, B_), 256, SMEM_CONV_>>>(conv_b);

    // offset path
    zfill_ls_kernel<<<(int)((((size_t)B_*HP_*WP_*KO_*2)/16 + 255)/256), 256>>>();
    pack_wo_kernel<<<(9*64*KO_ + 255)/256, 256>>>(off_w, off1_w, off2_w);
    mean_kernel<<<(total + 255)/256, 256>>>(x);
    gn_stats_kernel<<<32, 256>>>();
    gn_apply_kernel<<<(total + 255)/256, 256>>>(gn_gamma, gn_beta);
    norm_kernel<<<(B_*HW_ + 7)/8, 256>>>();
    sim_kernel<<<(B_*HW_ + 7)/8, 256>>>();
    offconv_mma_kernel<<<dim3(3, 120, B_), 256, SMEM_OFF_>>>(off_b, off1_b, off2_b);
    sample_kernel<<<(total + 255)/256, 256>>>(out);
}